// round 1
// baseline (speedup 1.0000x reference)
#include <cuda_runtime.h>
#include <math.h>

#define NN 20000
#define NE 640000
#define HD 4
#define CC 64
#define FO 256          // HD*CC, output width of both layers
#define NEG_SLOPE 0.2f

// ---------------- scratch (no allocations allowed) ----------------
__device__ float g_xh[(size_t)NN * FO];     // per-layer transformed features
__device__ float g_h[(size_t)NN * FO];      // layer-1 output
__device__ float g_alpha[(size_t)NE * HD];  // pre-softmax logits
__device__ float g_asrc[NN * HD];
__device__ float g_adst[NN * HD];
__device__ float g_ce[HD];
__device__ int   g_cnt[NN];
__device__ int   g_cursor[NN];
__device__ int   g_rowstart[NN + 1];
__device__ int   g_perm[NE];

// ---------------- CSR build ----------------
__global__ void zero_counts_kernel() {
    int i = blockIdx.x * blockDim.x + threadIdx.x;
    if (i < NN) { g_cnt[i] = 0; g_cursor[i] = 0; }
}

__global__ void hist_kernel(const int* __restrict__ dst) {
    int e = blockIdx.x * blockDim.x + threadIdx.x;
    if (e < NE) atomicAdd(&g_cnt[dst[e]], 1);
}

__global__ void scan_kernel() {
    __shared__ int buf[1024];
    __shared__ int carry_s;
    int tid = threadIdx.x;
    if (tid == 0) { carry_s = 0; g_rowstart[0] = 0; }
    __syncthreads();
    for (int base = 0; base < NN; base += 1024) {
        int i = base + tid;
        int v = (i < NN) ? g_cnt[i] : 0;
        buf[tid] = v;
        __syncthreads();
        for (int off = 1; off < 1024; off <<= 1) {
            int t = (tid >= off) ? buf[tid - off] : 0;
            __syncthreads();
            buf[tid] += t;
            __syncthreads();
        }
        int carry = carry_s;
        if (i < NN) g_rowstart[i + 1] = carry + buf[tid];
        __syncthreads();
        if (tid == 1023) carry_s = carry + buf[1023];
        __syncthreads();
    }
}

__global__ void scatter_kernel(const int* __restrict__ dst) {
    int e = blockIdx.x * blockDim.x + threadIdx.x;
    if (e < NE) {
        int d = dst[e];
        int pos = g_rowstart[d] + atomicAdd(&g_cursor[d], 1);
        g_perm[pos] = e;
    }
}

// ---------------- dense GEMM: C[M,Ncols] = A[M,K] @ B[K,Ncols] ----------------
// 128x128x8 tile, 8x8 microtile, 256 threads
__global__ __launch_bounds__(256) void gemm_kernel(
    const float* __restrict__ A, const float* __restrict__ B,
    float* __restrict__ C, int M, int K, int Ncols)
{
    __shared__ float As[8][132];
    __shared__ float Bs[8][128];
    int tid = threadIdx.x;
    int bn = blockIdx.x, bm = blockIdx.y;
    int tr = (tid / 16) * 8;
    int tc = (tid % 16) * 8;

    float acc[8][8];
#pragma unroll
    for (int i = 0; i < 8; i++)
#pragma unroll
        for (int j = 0; j < 8; j++) acc[i][j] = 0.f;

    int ar_row = tid >> 1;
    int ar_k4  = (tid & 1) * 4;
    int grow   = bm * 128 + ar_row;
    int bs_k   = tid >> 5;
    int bs_c   = (tid & 31) * 4;

    const float* Aptr = A + (size_t)grow * K + ar_k4;
    const float* Bptr = B + (size_t)bs_k * Ncols + bn * 128 + bs_c;

    for (int k0 = 0; k0 < K; k0 += 8) {
        float4 av = (grow < M) ? *(const float4*)(Aptr + k0)
                               : make_float4(0.f, 0.f, 0.f, 0.f);
        float4 bv = *(const float4*)(Bptr + (size_t)k0 * Ncols);
        As[ar_k4 + 0][ar_row] = av.x;
        As[ar_k4 + 1][ar_row] = av.y;
        As[ar_k4 + 2][ar_row] = av.z;
        As[ar_k4 + 3][ar_row] = av.w;
        *(float4*)&Bs[bs_k][bs_c] = bv;
        __syncthreads();
#pragma unroll
        for (int kk = 0; kk < 8; kk++) {
            float a0[8], b0[8];
#pragma unroll
            for (int i = 0; i < 8; i++) a0[i] = As[kk][tr + i];
#pragma unroll
            for (int j = 0; j < 8; j++) b0[j] = Bs[kk][tc + j];
#pragma unroll
            for (int i = 0; i < 8; i++)
#pragma unroll
                for (int j = 0; j < 8; j++) acc[i][j] += a0[i] * b0[j];
        }
        __syncthreads();
    }

#pragma unroll
    for (int i = 0; i < 8; i++) {
        int r = bm * 128 + tr + i;
        if (r < M) {
            *(float4*)(C + (size_t)r * Ncols + bn * 128 + tc) =
                make_float4(acc[i][0], acc[i][1], acc[i][2], acc[i][3]);
            *(float4*)(C + (size_t)r * Ncols + bn * 128 + tc + 4) =
                make_float4(acc[i][4], acc[i][5], acc[i][6], acc[i][7]);
        }
    }
}

// ---------------- ce[h] = sum_c W_e[0, h*64+c] * a_e[h,c] ----------------
__global__ void ce_kernel(const float* __restrict__ We, const float* __restrict__ ae) {
    int h = threadIdx.x >> 5, lane = threadIdx.x & 31;
    float v = We[h * 64 + lane] * ae[h * 64 + lane]
            + We[h * 64 + lane + 32] * ae[h * 64 + lane + 32];
#pragma unroll
    for (int o = 16; o; o >>= 1) v += __shfl_xor_sync(0xffffffffu, v, o);
    if (lane == 0) g_ce[h] = v;
}

// ---------------- per-node attention logits: warp per (n,h) ----------------
__global__ __launch_bounds__(256) void node_alpha_kernel(
    const float* __restrict__ asrc, const float* __restrict__ adst)
{
    int task = blockIdx.x * 8 + (threadIdx.x >> 5);
    int lane = threadIdx.x & 31;
    if (task >= NN * HD) return;
    int n = task >> 2, h = task & 3;
    const float* xr = g_xh + (size_t)n * FO + h * 64;
    float v0 = xr[lane], v1 = xr[lane + 32];
    float s = v0 * asrc[h * 64 + lane] + v1 * asrc[h * 64 + lane + 32];
    float d = v0 * adst[h * 64 + lane] + v1 * adst[h * 64 + lane + 32];
#pragma unroll
    for (int o = 16; o; o >>= 1) {
        s += __shfl_xor_sync(0xffffffffu, s, o);
        d += __shfl_xor_sync(0xffffffffu, d, o);
    }
    if (lane == 0) { g_asrc[n * 4 + h] = s; g_adst[n * 4 + h] = d; }
}

// ---------------- per-edge logits + leaky relu ----------------
__global__ void edge_alpha_kernel(const int* __restrict__ src,
                                  const int* __restrict__ dst,
                                  const float* __restrict__ edge_attr)
{
    int e = blockIdx.x * blockDim.x + threadIdx.x;
    if (e >= NE) return;
    int s = src[e], d = dst[e];
    float ea = edge_attr[e];
    float4 as = *(const float4*)(g_asrc + (size_t)s * 4);
    float4 ad = *(const float4*)(g_adst + (size_t)d * 4);
    float4 ce = *(const float4*)g_ce;
    float a0 = as.x + ad.x + ea * ce.x;
    float a1 = as.y + ad.y + ea * ce.y;
    float a2 = as.z + ad.z + ea * ce.z;
    float a3 = as.w + ad.w + ea * ce.w;
    a0 = a0 > 0.f ? a0 : NEG_SLOPE * a0;
    a1 = a1 > 0.f ? a1 : NEG_SLOPE * a1;
    a2 = a2 > 0.f ? a2 : NEG_SLOPE * a2;
    a3 = a3 > 0.f ? a3 : NEG_SLOPE * a3;
    *(float4*)(g_alpha + (size_t)e * 4) = make_float4(a0, a1, a2, a3);
}

// ---------------- segment softmax + weighted gather: warp per dst node ----------------
__global__ __launch_bounds__(256) void aggregate_kernel(
    const int* __restrict__ srcv,
    const float* __restrict__ edge_atten,
    const float* __restrict__ bias,
    float* __restrict__ out_h,
    float* __restrict__ out_w)
{
    int n = blockIdx.x * 8 + (threadIdx.x >> 5);
    int lane = threadIdx.x & 31;
    if (n >= NN) return;
    int r0 = g_rowstart[n], r1 = g_rowstart[n + 1];

    // pass 1: per-head max
    float mx0 = -3.4e38f, mx1 = -3.4e38f, mx2 = -3.4e38f, mx3 = -3.4e38f;
    for (int i = r0 + lane; i < r1; i += 32) {
        int e = g_perm[i];
        float4 a = *(const float4*)(g_alpha + (size_t)e * 4);
        mx0 = fmaxf(mx0, a.x); mx1 = fmaxf(mx1, a.y);
        mx2 = fmaxf(mx2, a.z); mx3 = fmaxf(mx3, a.w);
    }
#pragma unroll
    for (int o = 16; o; o >>= 1) {
        mx0 = fmaxf(mx0, __shfl_xor_sync(0xffffffffu, mx0, o));
        mx1 = fmaxf(mx1, __shfl_xor_sync(0xffffffffu, mx1, o));
        mx2 = fmaxf(mx2, __shfl_xor_sync(0xffffffffu, mx2, o));
        mx3 = fmaxf(mx3, __shfl_xor_sync(0xffffffffu, mx3, o));
    }

    // pass 2: per-head denom
    float dn0 = 0.f, dn1 = 0.f, dn2 = 0.f, dn3 = 0.f;
    for (int i = r0 + lane; i < r1; i += 32) {
        int e = g_perm[i];
        float4 a = *(const float4*)(g_alpha + (size_t)e * 4);
        dn0 += __expf(a.x - mx0); dn1 += __expf(a.y - mx1);
        dn2 += __expf(a.z - mx2); dn3 += __expf(a.w - mx3);
    }
#pragma unroll
    for (int o = 16; o; o >>= 1) {
        dn0 += __shfl_xor_sync(0xffffffffu, dn0, o);
        dn1 += __shfl_xor_sync(0xffffffffu, dn1, o);
        dn2 += __shfl_xor_sync(0xffffffffu, dn2, o);
        dn3 += __shfl_xor_sync(0xffffffffu, dn3, o);
    }
    float inv0 = 1.f / (dn0 + 1e-16f);
    float inv1 = 1.f / (dn1 + 1e-16f);
    float inv2 = 1.f / (dn2 + 1e-16f);
    float inv3 = 1.f / (dn3 + 1e-16f);

    // pass 3: serial over edges, whole warp covers the 256 feature cols
    float acc0 = 0.f, acc1 = 0.f, acc2 = 0.f, acc3 = 0.f;
    float acc4 = 0.f, acc5 = 0.f, acc6 = 0.f, acc7 = 0.f;
    for (int i = r0; i < r1; i++) {
        int e = g_perm[i];
        float4 a = *(const float4*)(g_alpha + (size_t)e * 4);
        float w0 = __expf(a.x - mx0) * inv0;
        float w1 = __expf(a.y - mx1) * inv1;
        float w2 = __expf(a.z - mx2) * inv2;
        float w3 = __expf(a.w - mx3) * inv3;
        if (lane == 0)
            *(float4*)(out_w + (size_t)e * 4) = make_float4(w0, w1, w2, w3);
        float at = edge_atten[e];
        w0 *= at; w1 *= at; w2 *= at; w3 *= at;
        int s = srcv[e];
        const float* xr = g_xh + (size_t)s * FO;
        acc0 += w0 * xr[lane];        acc1 += w0 * xr[lane + 32];
        acc2 += w1 * xr[64 + lane];   acc3 += w1 * xr[96 + lane];
        acc4 += w2 * xr[128 + lane];  acc5 += w2 * xr[160 + lane];
        acc6 += w3 * xr[192 + lane];  acc7 += w3 * xr[224 + lane];
    }

    float* orow = out_h + (size_t)n * FO;
    orow[lane]        = acc0 + bias[lane];
    orow[lane + 32]   = acc1 + bias[lane + 32];
    orow[lane + 64]   = acc2 + bias[lane + 64];
    orow[lane + 96]   = acc3 + bias[lane + 96];
    orow[lane + 128]  = acc4 + bias[lane + 128];
    orow[lane + 160]  = acc5 + bias[lane + 160];
    orow[lane + 192]  = acc6 + bias[lane + 192];
    orow[lane + 224]  = acc7 + bias[lane + 224];
}

// ---------------- launch ----------------
static void run_layer(const float* xin, int Kdim,
                      const float* W, const float* asrc, const float* adst,
                      const float* We, const float* ae, const float* b,
                      const int* src, const int* dst,
                      const float* edge_attr, const float* edge_atten,
                      float* out_h, float* out_w)
{
    float* xh;
    cudaGetSymbolAddress((void**)&xh, g_xh);
    dim3 ggrid((FO + 127) / 128, (NN + 127) / 128);
    gemm_kernel<<<ggrid, 256>>>(xin, W, xh, NN, Kdim, FO);
    ce_kernel<<<1, 128>>>(We, ae);
    node_alpha_kernel<<<(NN * HD + 7) / 8, 256>>>(asrc, adst);
    edge_alpha_kernel<<<(NE + 255) / 256, 256>>>(src, dst, edge_attr);
    aggregate_kernel<<<(NN + 7) / 8, 256>>>(src, edge_atten, b, out_h, out_w);
}

extern "C" void kernel_launch(void* const* d_in, const int* in_sizes, int n_in,
                              void* d_out, int out_size)
{
    const float* x          = (const float*)d_in[0];
    const int*   edge_index = (const int*)d_in[1];
    const float* edge_attr  = (const float*)d_in[3];
    const float* edge_atten = (const float*)d_in[4];
    const float* W1    = (const float*)d_in[5];
    const float* asrc1 = (const float*)d_in[6];
    const float* adst1 = (const float*)d_in[7];
    const float* We1   = (const float*)d_in[8];
    const float* ae1   = (const float*)d_in[9];
    const float* b1    = (const float*)d_in[10];
    const float* W2    = (const float*)d_in[11];
    const float* asrc2 = (const float*)d_in[12];
    const float* adst2 = (const float*)d_in[13];
    const float* We2   = (const float*)d_in[14];
    const float* ae2   = (const float*)d_in[15];
    const float* b2    = (const float*)d_in[16];

    const int* src = edge_index;
    const int* dst = edge_index + NE;

    float* out    = (float*)d_out;
    float* out_h  = out;                       // [NN, 256]
    float* out_w1 = out + (size_t)NN * FO;     // [NE, 4]
    float* out_w2 = out_w1 + (size_t)NE * HD;  // [NE, 4]

    float* hbuf;
    cudaGetSymbolAddress((void**)&hbuf, g_h);

    // CSR by dst (shared by both layers)
    zero_counts_kernel<<<(NN + 255) / 256, 256>>>();
    hist_kernel<<<(NE + 255) / 256, 256>>>(dst);
    scan_kernel<<<1, 1024>>>();
    scatter_kernel<<<(NE + 255) / 256, 256>>>(dst);

    // layer 1: x[NN,128] -> g_h[NN,256], alpha -> out_w1
    run_layer(x, 128, W1, asrc1, adst1, We1, ae1, b1,
              src, dst, edge_attr, edge_atten, hbuf, out_w1);
    // layer 2: g_h[NN,256] -> out_h[NN,256], alpha -> out_w2
    run_layer(hbuf, 256, W2, asrc2, adst2, We2, ae2, b2,
              src, dst, edge_attr, edge_atten, out_h, out_w2);
}

// round 2
// speedup vs baseline: 1.9622x; 1.9622x over previous
#include <cuda_runtime.h>
#include <math.h>

#define NN 20000
#define NE 640000
#define HD 4
#define CC 64
#define FO 256
#define NEG_SLOPE 0.2f

// ---------------- scratch ----------------
__device__ float g_xh[(size_t)NN * FO];
__device__ float g_h[(size_t)NN * FO];
__device__ float g_alpha_r[(size_t)NE * HD];   // CSR-ordered logits
__device__ float g_w_r[(size_t)NE * HD];       // CSR-ordered w*atten
__device__ int   g_src_r[NE];
__device__ int   g_dst_r[NE];
__device__ float g_atten_r[NE];
__device__ float g_asrc[NN * HD];
__device__ float g_adst[NN * HD];
__device__ float g_mx4[NN * HD];
__device__ float g_inv4[NN * HD];
__device__ float g_ce1[HD];
__device__ float g_ce2[HD];
__device__ int   g_cnt[NN];
__device__ int   g_cursor[NN];
__device__ int   g_rowstart[NN + 1];
__device__ int   g_perm[NE];

// ---------------- CSR build ----------------
__global__ void zero_counts_kernel() {
    int i = blockIdx.x * blockDim.x + threadIdx.x;
    if (i < NN) { g_cnt[i] = 0; g_cursor[i] = 0; }
}

__global__ void hist_kernel(const int* __restrict__ dst) {
    int e = blockIdx.x * blockDim.x + threadIdx.x;
    if (e < NE) atomicAdd(&g_cnt[dst[e]], 1);
}

// scan + fused ce precompute (both layers)
__global__ void scan_kernel(const float* __restrict__ We1, const float* __restrict__ ae1,
                            const float* __restrict__ We2, const float* __restrict__ ae2)
{
    int tid = threadIdx.x;
    int w = tid >> 5, lane = tid & 31;
    if (w < 8) {  // warps 0-3: ce1, warps 4-7: ce2
        const float* We = (w < 4) ? We1 : We2;
        const float* ae = (w < 4) ? ae1 : ae2;
        float* ce = (w < 4) ? g_ce1 : g_ce2;
        int h = w & 3;
        float v = We[h * 64 + lane] * ae[h * 64 + lane]
                + We[h * 64 + lane + 32] * ae[h * 64 + lane + 32];
#pragma unroll
        for (int o = 16; o; o >>= 1) v += __shfl_xor_sync(0xffffffffu, v, o);
        if (lane == 0) ce[h] = v;
    }

    __shared__ int buf[1024];
    __shared__ int carry_s;
    if (tid == 0) { carry_s = 0; g_rowstart[0] = 0; }
    __syncthreads();
    for (int base = 0; base < NN; base += 1024) {
        int i = base + tid;
        int v = (i < NN) ? g_cnt[i] : 0;
        buf[tid] = v;
        __syncthreads();
        for (int off = 1; off < 1024; off <<= 1) {
            int t = (tid >= off) ? buf[tid - off] : 0;
            __syncthreads();
            buf[tid] += t;
            __syncthreads();
        }
        int carry = carry_s;
        if (i < NN) g_rowstart[i + 1] = carry + buf[tid];
        __syncthreads();
        if (tid == 1023) carry_s = carry + buf[1023];
        __syncthreads();
    }
}

__global__ void scatter_kernel(const int* __restrict__ dst) {
    int e = blockIdx.x * blockDim.x + threadIdx.x;
    if (e < NE) {
        int d = dst[e];
        int pos = g_rowstart[d] + atomicAdd(&g_cursor[d], 1);
        g_perm[pos] = e;
    }
}

// ---------------- GEMM: C[M,N] = A[M,K] @ B[K,N], 128x128x8, reg-prefetch ----
__global__ __launch_bounds__(256) void gemm_kernel(
    const float* __restrict__ A, const float* __restrict__ B,
    float* __restrict__ C, int M, int K, int Ncols)
{
    __shared__ float As[8][132];
    __shared__ float Bs[8][128];
    int tid = threadIdx.x;
    int bn = blockIdx.x, bm = blockIdx.y;
    int tr = (tid / 16) * 8;
    int tc = (tid % 16) * 8;

    float acc[8][8];
#pragma unroll
    for (int i = 0; i < 8; i++)
#pragma unroll
        for (int j = 0; j < 8; j++) acc[i][j] = 0.f;

    int ar_row = tid >> 1;
    int ar_k4  = (tid & 1) * 4;
    int grow   = bm * 128 + ar_row;
    int bs_k   = tid >> 5;
    int bs_c   = (tid & 31) * 4;
    bool arow_ok = (grow < M);

    const float* Aptr = A + (size_t)grow * K + ar_k4;
    const float* Bptr = B + (size_t)bs_k * Ncols + bn * 128 + bs_c;

    float4 av = arow_ok ? *(const float4*)(Aptr) : make_float4(0.f, 0.f, 0.f, 0.f);
    float4 bv = *(const float4*)(Bptr);

    for (int k0 = 0; k0 < K; k0 += 8) {
        As[ar_k4 + 0][ar_row] = av.x;
        As[ar_k4 + 1][ar_row] = av.y;
        As[ar_k4 + 2][ar_row] = av.z;
        As[ar_k4 + 3][ar_row] = av.w;
        *(float4*)&Bs[bs_k][bs_c] = bv;
        __syncthreads();
        if (k0 + 8 < K) {  // prefetch next panel while computing this one
            av = arow_ok ? *(const float4*)(Aptr + k0 + 8)
                         : make_float4(0.f, 0.f, 0.f, 0.f);
            bv = *(const float4*)(Bptr + (size_t)(k0 + 8) * Ncols);
        }
#pragma unroll
        for (int kk = 0; kk < 8; kk++) {
            float a0[8], b0[8];
#pragma unroll
            for (int i = 0; i < 8; i++) a0[i] = As[kk][tr + i];
#pragma unroll
            for (int j = 0; j < 8; j++) b0[j] = Bs[kk][tc + j];
#pragma unroll
            for (int i = 0; i < 8; i++)
#pragma unroll
                for (int j = 0; j < 8; j++) acc[i][j] += a0[i] * b0[j];
        }
        __syncthreads();
    }

#pragma unroll
    for (int i = 0; i < 8; i++) {
        int r = bm * 128 + tr + i;
        if (r < M) {
            *(float4*)(C + (size_t)r * Ncols + bn * 128 + tc) =
                make_float4(acc[i][0], acc[i][1], acc[i][2], acc[i][3]);
            *(float4*)(C + (size_t)r * Ncols + bn * 128 + tc + 4) =
                make_float4(acc[i][4], acc[i][5], acc[i][6], acc[i][7]);
        }
    }
}

// ---------------- per-node attention dots ----------------
__global__ __launch_bounds__(256) void node_alpha_kernel(
    const float* __restrict__ asrc, const float* __restrict__ adst)
{
    int task = blockIdx.x * 8 + (threadIdx.x >> 5);
    int lane = threadIdx.x & 31;
    if (task >= NN * HD) return;
    int n = task >> 2, h = task & 3;
    const float* xr = g_xh + (size_t)n * FO + h * 64;
    float v0 = xr[lane], v1 = xr[lane + 32];
    float s = v0 * asrc[h * 64 + lane] + v1 * asrc[h * 64 + lane + 32];
    float d = v0 * adst[h * 64 + lane] + v1 * adst[h * 64 + lane + 32];
#pragma unroll
    for (int o = 16; o; o >>= 1) {
        s += __shfl_xor_sync(0xffffffffu, s, o);
        d += __shfl_xor_sync(0xffffffffu, d, o);
    }
    if (lane == 0) { g_asrc[n * 4 + h] = s; g_adst[n * 4 + h] = d; }
}

// ---------------- edge logits, written in CSR order ----------------
__global__ void edge_alpha_kernel(const int* __restrict__ src,
                                  const int* __restrict__ dst,
                                  const float* __restrict__ edge_attr,
                                  const float* __restrict__ edge_atten,
                                  const float* __restrict__ ce)
{
    int p = blockIdx.x * blockDim.x + threadIdx.x;
    if (p >= NE) return;
    int e = g_perm[p];
    int s = src[e], d = dst[e];
    float ea = edge_attr[e];
    float4 as = *(const float4*)(g_asrc + (size_t)s * 4);
    float4 ad = *(const float4*)(g_adst + (size_t)d * 4);
    float4 c  = *(const float4*)ce;
    float a0 = as.x + ad.x + ea * c.x;
    float a1 = as.y + ad.y + ea * c.y;
    float a2 = as.z + ad.z + ea * c.z;
    float a3 = as.w + ad.w + ea * c.w;
    a0 = a0 > 0.f ? a0 : NEG_SLOPE * a0;
    a1 = a1 > 0.f ? a1 : NEG_SLOPE * a1;
    a2 = a2 > 0.f ? a2 : NEG_SLOPE * a2;
    a3 = a3 > 0.f ? a3 : NEG_SLOPE * a3;
    *(float4*)(g_alpha_r + (size_t)p * 4) = make_float4(a0, a1, a2, a3);
    g_src_r[p] = s;
    g_dst_r[p] = d;
    g_atten_r[p] = edge_atten[e];
}

// ---------------- per-node max + denom (coalesced reads) ----------------
__global__ __launch_bounds__(256) void node_maxd_kernel()
{
    int n = blockIdx.x * 8 + (threadIdx.x >> 5);
    int lane = threadIdx.x & 31;
    if (n >= NN) return;
    int r0 = g_rowstart[n], r1 = g_rowstart[n + 1];

    float mx0 = -3.4e38f, mx1 = -3.4e38f, mx2 = -3.4e38f, mx3 = -3.4e38f;
    for (int i = r0 + lane; i < r1; i += 32) {
        float4 a = *(const float4*)(g_alpha_r + (size_t)i * 4);
        mx0 = fmaxf(mx0, a.x); mx1 = fmaxf(mx1, a.y);
        mx2 = fmaxf(mx2, a.z); mx3 = fmaxf(mx3, a.w);
    }
#pragma unroll
    for (int o = 16; o; o >>= 1) {
        mx0 = fmaxf(mx0, __shfl_xor_sync(0xffffffffu, mx0, o));
        mx1 = fmaxf(mx1, __shfl_xor_sync(0xffffffffu, mx1, o));
        mx2 = fmaxf(mx2, __shfl_xor_sync(0xffffffffu, mx2, o));
        mx3 = fmaxf(mx3, __shfl_xor_sync(0xffffffffu, mx3, o));
    }
    float dn0 = 0.f, dn1 = 0.f, dn2 = 0.f, dn3 = 0.f;
    for (int i = r0 + lane; i < r1; i += 32) {
        float4 a = *(const float4*)(g_alpha_r + (size_t)i * 4);
        dn0 += __expf(a.x - mx0); dn1 += __expf(a.y - mx1);
        dn2 += __expf(a.z - mx2); dn3 += __expf(a.w - mx3);
    }
#pragma unroll
    for (int o = 16; o; o >>= 1) {
        dn0 += __shfl_xor_sync(0xffffffffu, dn0, o);
        dn1 += __shfl_xor_sync(0xffffffffu, dn1, o);
        dn2 += __shfl_xor_sync(0xffffffffu, dn2, o);
        dn3 += __shfl_xor_sync(0xffffffffu, dn3, o);
    }
    if (lane == 0) {
        *(float4*)(g_mx4 + (size_t)n * 4)  = make_float4(mx0, mx1, mx2, mx3);
        *(float4*)(g_inv4 + (size_t)n * 4) =
            make_float4(1.f / (dn0 + 1e-16f), 1.f / (dn1 + 1e-16f),
                        1.f / (dn2 + 1e-16f), 1.f / (dn3 + 1e-16f));
    }
}

// ---------------- edge-parallel softmax weights ----------------
__global__ void edge_weight_kernel(float* __restrict__ out_w)
{
    int p = blockIdx.x * blockDim.x + threadIdx.x;
    if (p >= NE) return;
    float4 a  = *(const float4*)(g_alpha_r + (size_t)p * 4);
    int d = g_dst_r[p];
    float4 mx = *(const float4*)(g_mx4 + (size_t)d * 4);
    float4 iv = *(const float4*)(g_inv4 + (size_t)d * 4);
    float w0 = __expf(a.x - mx.x) * iv.x;
    float w1 = __expf(a.y - mx.y) * iv.y;
    float w2 = __expf(a.z - mx.z) * iv.z;
    float w3 = __expf(a.w - mx.w) * iv.w;
    int e = g_perm[p];
    *(float4*)(out_w + (size_t)e * 4) = make_float4(w0, w1, w2, w3);
    float at = g_atten_r[p];
    *(float4*)(g_w_r + (size_t)p * 4) = make_float4(w0 * at, w1 * at, w2 * at, w3 * at);
}

// ---------------- weighted gather, warp per dst node ----------------
__global__ __launch_bounds__(256) void aggregate_kernel(
    const float* __restrict__ bias, float* __restrict__ out_h)
{
    int n = blockIdx.x * 8 + (threadIdx.x >> 5);
    int lane = threadIdx.x & 31;
    if (n >= NN) return;
    int r0 = g_rowstart[n], r1 = g_rowstart[n + 1];
    bool hi = lane >= 16;

    float4 accA = make_float4(0.f, 0.f, 0.f, 0.f);
    float4 accB = make_float4(0.f, 0.f, 0.f, 0.f);

    if (r0 < r1) {
        float4 w4 = *(const float4*)(g_w_r + (size_t)r0 * 4);
        int s = g_src_r[r0];
        for (int i = r0; i < r1; i++) {
            float4 w4c = w4;
            int sc = s;
            if (i + 1 < r1) {
                w4 = *(const float4*)(g_w_r + (size_t)(i + 1) * 4);
                s  = g_src_r[i + 1];
            }
            float wA = hi ? w4c.y : w4c.x;
            float wB = hi ? w4c.w : w4c.z;
            const float* xr = g_xh + (size_t)sc * FO;
            float4 vA = *(const float4*)(xr + lane * 4);
            float4 vB = *(const float4*)(xr + 128 + lane * 4);
            accA.x += wA * vA.x; accA.y += wA * vA.y;
            accA.z += wA * vA.z; accA.w += wA * vA.w;
            accB.x += wB * vB.x; accB.y += wB * vB.y;
            accB.z += wB * vB.z; accB.w += wB * vB.w;
        }
    }

    float4 bA = *(const float4*)(bias + lane * 4);
    float4 bB = *(const float4*)(bias + 128 + lane * 4);
    float* orow = out_h + (size_t)n * FO;
    *(float4*)(orow + lane * 4) =
        make_float4(accA.x + bA.x, accA.y + bA.y, accA.z + bA.z, accA.w + bA.w);
    *(float4*)(orow + 128 + lane * 4) =
        make_float4(accB.x + bB.x, accB.y + bB.y, accB.z + bB.z, accB.w + bB.w);
}

// ---------------- launch ----------------
static void run_layer(const float* xin, int Kdim,
                      const float* W, const float* asrc, const float* adst,
                      const float* ce_dev, const float* b,
                      const int* src, const int* dst,
                      const float* edge_attr, const float* edge_atten,
                      float* out_h, float* out_w)
{
    float* xh;
    cudaGetSymbolAddress((void**)&xh, g_xh);
    dim3 ggrid((FO + 127) / 128, (NN + 127) / 128);
    gemm_kernel<<<ggrid, 256>>>(xin, W, xh, NN, Kdim, FO);
    node_alpha_kernel<<<(NN * HD + 7) / 8, 256>>>(asrc, adst);
    edge_alpha_kernel<<<(NE + 255) / 256, 256>>>(src, dst, edge_attr, edge_atten, ce_dev);
    node_maxd_kernel<<<(NN + 7) / 8, 256>>>();
    edge_weight_kernel<<<(NE + 255) / 256, 256>>>(out_w);
    aggregate_kernel<<<(NN + 7) / 8, 256>>>(b, out_h);
}

extern "C" void kernel_launch(void* const* d_in, const int* in_sizes, int n_in,
                              void* d_out, int out_size)
{
    const float* x          = (const float*)d_in[0];
    const int*   edge_index = (const int*)d_in[1];
    const float* edge_attr  = (const float*)d_in[3];
    const float* edge_atten = (const float*)d_in[4];
    const float* W1    = (const float*)d_in[5];
    const float* asrc1 = (const float*)d_in[6];
    const float* adst1 = (const float*)d_in[7];
    const float* We1   = (const float*)d_in[8];
    const float* ae1   = (const float*)d_in[9];
    const float* b1    = (const float*)d_in[10];
    const float* W2    = (const float*)d_in[11];
    const float* asrc2 = (const float*)d_in[12];
    const float* adst2 = (const float*)d_in[13];
    const float* We2   = (const float*)d_in[14];
    const float* ae2   = (const float*)d_in[15];
    const float* b2    = (const float*)d_in[16];

    const int* src = edge_index;
    const int* dst = edge_index + NE;

    float* out    = (float*)d_out;
    float* out_h  = out;
    float* out_w1 = out + (size_t)NN * FO;
    float* out_w2 = out_w1 + (size_t)NE * HD;

    float* hbuf; cudaGetSymbolAddress((void**)&hbuf, g_h);
    float* ce1;  cudaGetSymbolAddress((void**)&ce1, g_ce1);
    float* ce2;  cudaGetSymbolAddress((void**)&ce2, g_ce2);

    // CSR by dst (shared by both layers) + fused ce precompute
    zero_counts_kernel<<<(NN + 255) / 256, 256>>>();
    hist_kernel<<<(NE + 255) / 256, 256>>>(dst);
    scan_kernel<<<1, 1024>>>(We1, ae1, We2, ae2);
    scatter_kernel<<<(NE + 255) / 256, 256>>>(dst);

    run_layer(x, 128, W1, asrc1, adst1, ce1, b1,
              src, dst, edge_attr, edge_atten, hbuf, out_w1);
    run_layer(hbuf, 256, W2, asrc2, adst2, ce2, b2,
              src, dst, edge_attr, edge_atten, out_h, out_w2);
}

// round 5
// speedup vs baseline: 2.2764x; 1.1601x over previous
#include <cuda_runtime.h>
#include <cuda_bf16.h>
#include <math.h>
#include <stdint.h>

#define NN 20000
#define NE 640000
#define HD 4
#define CC 64
#define FO 256
#define NEG_SLOPE 0.2f

// ================= scratch =================
__device__ float g_xh[(size_t)NN * FO];
__device__ float g_h[(size_t)NN * FO];
__device__ float g_alpha_r[(size_t)NE * HD];
__device__ float g_w_r[(size_t)NE * HD];
__device__ int   g_src_r[NE];
__device__ int   g_dst_r[NE];
__device__ float g_atten_r[NE];
__device__ float g_asrc[NN * HD];
__device__ float g_adst[NN * HD];
__device__ float g_mx4[NN * HD];
__device__ float g_inv4[NN * HD];
__device__ float g_ce1[HD];
__device__ float g_ce2[HD];
__device__ int   g_cnt[NN];
__device__ int   g_cursor[NN];
__device__ int   g_rowstart[NN + 1];
__device__ int   g_perm[NE];
__device__ __align__(16) __nv_bfloat16 g_Wt1hi[256 * 128];
__device__ __align__(16) __nv_bfloat16 g_Wt1lo[256 * 128];
__device__ __align__(16) __nv_bfloat16 g_Wt2hi[256 * 256];
__device__ __align__(16) __nv_bfloat16 g_Wt2lo[256 * 256];

// ================= CSR build =================
__global__ void zero_counts_kernel() {
    int i = blockIdx.x * blockDim.x + threadIdx.x;
    if (i < NN) { g_cnt[i] = 0; g_cursor[i] = 0; }
}

__global__ void hist_kernel(const int* __restrict__ dst) {
    int e = blockIdx.x * blockDim.x + threadIdx.x;
    if (e < NE) atomicAdd(&g_cnt[dst[e]], 1);
}

__global__ void scan_kernel(const float* __restrict__ We1, const float* __restrict__ ae1,
                            const float* __restrict__ We2, const float* __restrict__ ae2)
{
    int tid = threadIdx.x;
    int w = tid >> 5, lane = tid & 31;
    if (w < 8) {
        const float* We = (w < 4) ? We1 : We2;
        const float* ae = (w < 4) ? ae1 : ae2;
        float* ce = (w < 4) ? g_ce1 : g_ce2;
        int h = w & 3;
        float v = We[h * 64 + lane] * ae[h * 64 + lane]
                + We[h * 64 + lane + 32] * ae[h * 64 + lane + 32];
#pragma unroll
        for (int o = 16; o; o >>= 1) v += __shfl_xor_sync(0xffffffffu, v, o);
        if (lane == 0) ce[h] = v;
    }

    __shared__ int buf[1024];
    __shared__ int carry_s;
    if (tid == 0) { carry_s = 0; g_rowstart[0] = 0; }
    __syncthreads();
    for (int base = 0; base < NN; base += 1024) {
        int i = base + tid;
        int v = (i < NN) ? g_cnt[i] : 0;
        buf[tid] = v;
        __syncthreads();
        for (int off = 1; off < 1024; off <<= 1) {
            int t = (tid >= off) ? buf[tid - off] : 0;
            __syncthreads();
            buf[tid] += t;
            __syncthreads();
        }
        int carry = carry_s;
        if (i < NN) g_rowstart[i + 1] = carry + buf[tid];
        __syncthreads();
        if (tid == 1023) carry_s = carry + buf[1023];
        __syncthreads();
    }
}

__global__ void scatter_kernel(const int* __restrict__ dst) {
    int e = blockIdx.x * blockDim.x + threadIdx.x;
    if (e < NE) {
        int d = dst[e];
        int pos = g_rowstart[d] + atomicAdd(&g_cursor[d], 1);
        g_perm[pos] = e;
    }
}

// ================= W transpose + bf16 split =================
__global__ void convert_w_kernel(const float* __restrict__ W, int K,
                                 __nv_bfloat16* __restrict__ Whi,
                                 __nv_bfloat16* __restrict__ Wlo)
{
    int idx = blockIdx.x * blockDim.x + threadIdx.x;
    if (idx >= K * 256) return;
    int k = idx >> 8, n = idx & 255;
    float v = W[idx];
    __nv_bfloat16 h = __float2bfloat16_rn(v);
    float r = v - __bfloat162float(h);
    Whi[n * K + k] = h;
    Wlo[n * K + k] = __float2bfloat16_rn(r);
}

// ================= split-bf16 mma.sync GEMM =================
// C[M,256] = A[M,K] @ W[K,256]; Bhi/Blo pre-transposed [256,K].
// CTA 128x128 (grid.y = N half), 8 warps 4x2, warp 32x64, K chunk 32.
__device__ __forceinline__ void mma_bf16(float* c, uint32_t a0, uint32_t a1,
                                         uint32_t a2, uint32_t a3,
                                         uint32_t b0, uint32_t b1)
{
    asm volatile(
        "mma.sync.aligned.m16n8k16.row.col.f32.bf16.bf16.f32 "
        "{%0,%1,%2,%3}, {%4,%5,%6,%7}, {%8,%9}, {%0,%1,%2,%3};"
        : "+f"(c[0]), "+f"(c[1]), "+f"(c[2]), "+f"(c[3])
        : "r"(a0), "r"(a1), "r"(a2), "r"(a3), "r"(b0), "r"(b1));
}

#define KP 20  // uint32 pitch per 32-k row (16 data + 4 pad; 80B = 16B-aligned rows)

__global__ __launch_bounds__(256) void gemm_mma_kernel(
    const float* __restrict__ A,
    const __nv_bfloat16* __restrict__ Bhi,
    const __nv_bfloat16* __restrict__ Blo,
    float* __restrict__ C, int K)
{
    __shared__ uint32_t As_hi[128][KP];
    __shared__ uint32_t As_lo[128][KP];
    __shared__ uint32_t Bs_hi[128][KP];
    __shared__ uint32_t Bs_lo[128][KP];

    int tid = threadIdx.x;
    int wid = tid >> 5, lane = tid & 31;
    int m0c = blockIdx.x * 128, n0c = blockIdx.y * 128;
    int wm0 = (wid >> 1) * 32, wn0 = (wid & 1) * 64;
    int lq = lane >> 2, lr = lane & 3;

    float acc[2][8][4];
#pragma unroll
    for (int mt = 0; mt < 2; mt++)
#pragma unroll
        for (int nt = 0; nt < 8; nt++)
#pragma unroll
            for (int j = 0; j < 4; j++) acc[mt][nt][j] = 0.f;

    // A load mapping: 2 threads per row, each covers 16 k (4 float4)
    int a_row = tid >> 1, a_half = tid & 1;
    int a_grow = m0c + a_row;
    bool a_ok = (a_grow < NN);
    // B load mapping: 1 thread per row-half: 16 k (2 uint4 per buffer)
    int b_row = tid & 127, b_half = tid >> 7;

    int nchunks = K >> 5;
    for (int c = 0; c < nchunks; c++) {
        int k0 = c << 5;
        // --- A: fp32 -> hi/lo bf16 ---
#pragma unroll
        for (int j = 0; j < 4; j++) {
            int kk = a_half * 16 + j * 4;
            float4 v = a_ok ? *(const float4*)(A + (size_t)a_grow * K + k0 + kk)
                            : make_float4(0.f, 0.f, 0.f, 0.f);
            __nv_bfloat162 h01 = __floats2bfloat162_rn(v.x, v.y);
            __nv_bfloat162 h23 = __floats2bfloat162_rn(v.z, v.w);
            __nv_bfloat162 l01 = __floats2bfloat162_rn(v.x - __low2float(h01),
                                                       v.y - __high2float(h01));
            __nv_bfloat162 l23 = __floats2bfloat162_rn(v.z - __low2float(h23),
                                                       v.w - __high2float(h23));
            int ci = kk >> 1;
            As_hi[a_row][ci]     = *(uint32_t*)&h01;
            As_hi[a_row][ci + 1] = *(uint32_t*)&h23;
            As_lo[a_row][ci]     = *(uint32_t*)&l01;
            As_lo[a_row][ci + 1] = *(uint32_t*)&l23;
        }
        // --- B: bf16 hi/lo [256,K] ---
        {
            const __nv_bfloat16* ph = Bhi + (size_t)(n0c + b_row) * K + k0 + b_half * 16;
            const __nv_bfloat16* pl = Blo + (size_t)(n0c + b_row) * K + k0 + b_half * 16;
            uint4 vh0 = *(const uint4*)ph;
            uint4 vh1 = *(const uint4*)(ph + 8);
            uint4 vl0 = *(const uint4*)pl;
            uint4 vl1 = *(const uint4*)(pl + 8);
            int ci = b_half * 8;
            *(uint4*)&Bs_hi[b_row][ci]     = vh0;
            *(uint4*)&Bs_hi[b_row][ci + 4] = vh1;
            *(uint4*)&Bs_lo[b_row][ci]     = vl0;
            *(uint4*)&Bs_lo[b_row][ci + 4] = vl1;
        }
        __syncthreads();

#pragma unroll
        for (int ks = 0; ks < 2; ks++) {
            int kb = ks * 8 + lr;
            uint32_t ah[2][4], al[2][4];
#pragma unroll
            for (int mt = 0; mt < 2; mt++) {
                int ra = wm0 + mt * 16 + lq, rb = ra + 8;
                ah[mt][0] = As_hi[ra][kb];     ah[mt][1] = As_hi[rb][kb];
                ah[mt][2] = As_hi[ra][kb + 4]; ah[mt][3] = As_hi[rb][kb + 4];
                al[mt][0] = As_lo[ra][kb];     al[mt][1] = As_lo[rb][kb];
                al[mt][2] = As_lo[ra][kb + 4]; al[mt][3] = As_lo[rb][kb + 4];
            }
#pragma unroll
            for (int nt = 0; nt < 8; nt++) {
                int nr = wn0 + nt * 8 + lq;
                uint32_t bh0 = Bs_hi[nr][kb], bh1 = Bs_hi[nr][kb + 4];
                uint32_t bl0 = Bs_lo[nr][kb], bl1 = Bs_lo[nr][kb + 4];
#pragma unroll
                for (int mt = 0; mt < 2; mt++) {
                    mma_bf16(acc[mt][nt], ah[mt][0], ah[mt][1], ah[mt][2], ah[mt][3], bh0, bh1);
                    mma_bf16(acc[mt][nt], ah[mt][0], ah[mt][1], ah[mt][2], ah[mt][3], bl0, bl1);
                    mma_bf16(acc[mt][nt], al[mt][0], al[mt][1], al[mt][2], al[mt][3], bh0, bh1);
                }
            }
        }
        __syncthreads();
    }

    // store
#pragma unroll
    for (int mt = 0; mt < 2; mt++) {
        int row0 = m0c + wm0 + mt * 16 + lq;
#pragma unroll
        for (int nt = 0; nt < 8; nt++) {
            int col = n0c + wn0 + nt * 8 + 2 * lr;
            if (row0 < NN)
                *(float2*)(C + (size_t)row0 * FO + col) =
                    make_float2(acc[mt][nt][0], acc[mt][nt][1]);
            if (row0 + 8 < NN)
                *(float2*)(C + (size_t)(row0 + 8) * FO + col) =
                    make_float2(acc[mt][nt][2], acc[mt][nt][3]);
        }
    }
}

// ================= per-node attention dots =================
__global__ __launch_bounds__(256) void node_alpha_kernel(
    const float* __restrict__ asrc, const float* __restrict__ adst)
{
    int task = blockIdx.x * 8 + (threadIdx.x >> 5);
    int lane = threadIdx.x & 31;
    if (task >= NN * HD) return;
    int n = task >> 2, h = task & 3;
    const float* xr = g_xh + (size_t)n * FO + h * 64;
    float v0 = xr[lane], v1 = xr[lane + 32];
    float s = v0 * asrc[h * 64 + lane] + v1 * asrc[h * 64 + lane + 32];
    float d = v0 * adst[h * 64 + lane] + v1 * adst[h * 64 + lane + 32];
#pragma unroll
    for (int o = 16; o; o >>= 1) {
        s += __shfl_xor_sync(0xffffffffu, s, o);
        d += __shfl_xor_sync(0xffffffffu, d, o);
    }
    if (lane == 0) { g_asrc[n * 4 + h] = s; g_adst[n * 4 + h] = d; }
}

// ================= edge logits, CSR order =================
__global__ void edge_alpha_kernel(const int* __restrict__ src,
                                  const int* __restrict__ dst,
                                  const float* __restrict__ edge_attr,
                                  const float* __restrict__ edge_atten,
                                  const float* __restrict__ ce)
{
    int p = blockIdx.x * blockDim.x + threadIdx.x;
    if (p >= NE) return;
    int e = g_perm[p];
    int s = src[e], d = dst[e];
    float ea = edge_attr[e];
    float4 as = *(const float4*)(g_asrc + (size_t)s * 4);
    float4 ad = *(const float4*)(g_adst + (size_t)d * 4);
    float4 c  = *(const float4*)ce;
    float a0 = as.x + ad.x + ea * c.x;
    float a1 = as.y + ad.y + ea * c.y;
    float a2 = as.z + ad.z + ea * c.z;
    float a3 = as.w + ad.w + ea * c.w;
    a0 = a0 > 0.f ? a0 : NEG_SLOPE * a0;
    a1 = a1 > 0.f ? a1 : NEG_SLOPE * a1;
    a2 = a2 > 0.f ? a2 : NEG_SLOPE * a2;
    a3 = a3 > 0.f ? a3 : NEG_SLOPE * a3;
    *(float4*)(g_alpha_r + (size_t)p * 4) = make_float4(a0, a1, a2, a3);
    g_src_r[p] = s;
    g_dst_r[p] = d;
    g_atten_r[p] = edge_atten[e];
}

// ================= per-node max + denom =================
__global__ __launch_bounds__(256) void node_maxd_kernel()
{
    int n = blockIdx.x * 8 + (threadIdx.x >> 5);
    int lane = threadIdx.x & 31;
    if (n >= NN) return;
    int r0 = g_rowstart[n], r1 = g_rowstart[n + 1];

    float mx0 = -3.4e38f, mx1 = -3.4e38f, mx2 = -3.4e38f, mx3 = -3.4e38f;
    for (int i = r0 + lane; i < r1; i += 32) {
        float4 a = *(const float4*)(g_alpha_r + (size_t)i * 4);
        mx0 = fmaxf(mx0, a.x); mx1 = fmaxf(mx1, a.y);
        mx2 = fmaxf(mx2, a.z); mx3 = fmaxf(mx3, a.w);
    }
#pragma unroll
    for (int o = 16; o; o >>= 1) {
        mx0 = fmaxf(mx0, __shfl_xor_sync(0xffffffffu, mx0, o));
        mx1 = fmaxf(mx1, __shfl_xor_sync(0xffffffffu, mx1, o));
        mx2 = fmaxf(mx2, __shfl_xor_sync(0xffffffffu, mx2, o));
        mx3 = fmaxf(mx3, __shfl_xor_sync(0xffffffffu, mx3, o));
    }
    float dn0 = 0.f, dn1 = 0.f, dn2 = 0.f, dn3 = 0.f;
    for (int i = r0 + lane; i < r1; i += 32) {
        float4 a = *(const float4*)(g_alpha_r + (size_t)i * 4);
        dn0 += __expf(a.x - mx0); dn1 += __expf(a.y - mx1);
        dn2 += __expf(a.z - mx2); dn3 += __expf(a.w - mx3);
    }
#pragma unroll
    for (int o = 16; o; o >>= 1) {
        dn0 += __shfl_xor_sync(0xffffffffu, dn0, o);
        dn1 += __shfl_xor_sync(0xffffffffu, dn1, o);
        dn2 += __shfl_xor_sync(0xffffffffu, dn2, o);
        dn3 += __shfl_xor_sync(0xffffffffu, dn3, o);
    }
    if (lane == 0) {
        *(float4*)(g_mx4 + (size_t)n * 4)  = make_float4(mx0, mx1, mx2, mx3);
        *(float4*)(g_inv4 + (size_t)n * 4) =
            make_float4(1.f / (dn0 + 1e-16f), 1.f / (dn1 + 1e-16f),
                        1.f / (dn2 + 1e-16f), 1.f / (dn3 + 1e-16f));
    }
}

// ================= edge-parallel softmax weights =================
__global__ void edge_weight_kernel(float* __restrict__ out_w)
{
    int p = blockIdx.x * blockDim.x + threadIdx.x;
    if (p >= NE) return;
    float4 a  = *(const float4*)(g_alpha_r + (size_t)p * 4);
    int d = g_dst_r[p];
    float4 mx = *(const float4*)(g_mx4 + (size_t)d * 4);
    float4 iv = *(const float4*)(g_inv4 + (size_t)d * 4);
    float w0 = __expf(a.x - mx.x) * iv.x;
    float w1 = __expf(a.y - mx.y) * iv.y;
    float w2 = __expf(a.z - mx.z) * iv.z;
    float w3 = __expf(a.w - mx.w) * iv.w;
    int e = g_perm[p];
    *(float4*)(out_w + (size_t)e * 4) = make_float4(w0, w1, w2, w3);
    float at = g_atten_r[p];
    *(float4*)(g_w_r + (size_t)p * 4) = make_float4(w0 * at, w1 * at, w2 * at, w3 * at);
}

// ================= weighted gather, warp per dst =================
__global__ __launch_bounds__(256) void aggregate_kernel(
    const float* __restrict__ bias, float* __restrict__ out_h)
{
    int n = blockIdx.x * 8 + (threadIdx.x >> 5);
    int lane = threadIdx.x & 31;
    if (n >= NN) return;
    int r0 = g_rowstart[n], r1 = g_rowstart[n + 1];
    bool hi = lane >= 16;

    float4 accA = make_float4(0.f, 0.f, 0.f, 0.f);
    float4 accB = make_float4(0.f, 0.f, 0.f, 0.f);

    if (r0 < r1) {
        float4 w4 = *(const float4*)(g_w_r + (size_t)r0 * 4);
        int s = g_src_r[r0];
        for (int i = r0; i < r1; i++) {
            float4 w4c = w4;
            int sc = s;
            if (i + 1 < r1) {
                w4 = *(const float4*)(g_w_r + (size_t)(i + 1) * 4);
                s  = g_src_r[i + 1];
            }
            float wA = hi ? w4c.y : w4c.x;
            float wB = hi ? w4c.w : w4c.z;
            const float* xr = g_xh + (size_t)sc * FO;
            float4 vA = *(const float4*)(xr + lane * 4);
            float4 vB = *(const float4*)(xr + 128 + lane * 4);
            accA.x += wA * vA.x; accA.y += wA * vA.y;
            accA.z += wA * vA.z; accA.w += wA * vA.w;
            accB.x += wB * vB.x; accB.y += wB * vB.y;
            accB.z += wB * vB.z; accB.w += wB * vB.w;
        }
    }

    float4 bA = *(const float4*)(bias + lane * 4);
    float4 bB = *(const float4*)(bias + 128 + lane * 4);
    float* orow = out_h + (size_t)n * FO;
    *(float4*)(orow + lane * 4) =
        make_float4(accA.x + bA.x, accA.y + bA.y, accA.z + bA.z, accA.w + bA.w);
    *(float4*)(orow + 128 + lane * 4) =
        make_float4(accB.x + bB.x, accB.y + bB.y, accB.z + bB.z, accB.w + bB.w);
}

// ================= launch =================
static void run_layer(const float* xin, int Kdim,
                      const __nv_bfloat16* Whi, const __nv_bfloat16* Wlo,
                      const float* asrc, const float* adst,
                      const float* ce_dev, const float* b,
                      const int* src, const int* dst,
                      const float* edge_attr, const float* edge_atten,
                      float* out_h, float* out_w)
{
    float* xh;
    cudaGetSymbolAddress((void**)&xh, g_xh);
    dim3 ggrid((NN + 127) / 128, 2);
    gemm_mma_kernel<<<ggrid, 256>>>(xin, Whi, Wlo, xh, Kdim);
    node_alpha_kernel<<<(NN * HD + 7) / 8, 256>>>(asrc, adst);
    edge_alpha_kernel<<<(NE + 255) / 256, 256>>>(src, dst, edge_attr, edge_atten, ce_dev);
    node_maxd_kernel<<<(NN + 7) / 8, 256>>>();
    edge_weight_kernel<<<(NE + 255) / 256, 256>>>(out_w);
    aggregate_kernel<<<(NN + 7) / 8, 256>>>(b, out_h);
}

extern "C" void kernel_launch(void* const* d_in, const int* in_sizes, int n_in,
                              void* d_out, int out_size)
{
    const float* x          = (const float*)d_in[0];
    const int*   edge_index = (const int*)d_in[1];
    const float* edge_attr  = (const float*)d_in[3];
    const float* edge_atten = (const float*)d_in[4];
    const float* W1    = (const float*)d_in[5];
    const float* asrc1 = (const float*)d_in[6];
    const float* adst1 = (const float*)d_in[7];
    const float* We1   = (const float*)d_in[8];
    const float* ae1   = (const float*)d_in[9];
    const float* b1    = (const float*)d_in[10];
    const float* W2    = (const float*)d_in[11];
    const float* asrc2 = (const float*)d_in[12];
    const float* adst2 = (const float*)d_in[13];
    const float* We2   = (const float*)d_in[14];
    const float* ae2   = (const float*)d_in[15];
    const float* b2    = (const float*)d_in[16];

    const int* src = edge_index;
    const int* dst = edge_index + NE;

    float* out    = (float*)d_out;
    float* out_h  = out;
    float* out_w1 = out + (size_t)NN * FO;
    float* out_w2 = out_w1 + (size_t)NE * HD;

    float* hbuf; cudaGetSymbolAddress((void**)&hbuf, g_h);
    float* ce1;  cudaGetSymbolAddress((void**)&ce1, g_ce1);
    float* ce2;  cudaGetSymbolAddress((void**)&ce2, g_ce2);
    __nv_bfloat16 *wt1h, *wt1l, *wt2h, *wt2l;
    cudaGetSymbolAddress((void**)&wt1h, g_Wt1hi);
    cudaGetSymbolAddress((void**)&wt1l, g_Wt1lo);
    cudaGetSymbolAddress((void**)&wt2h, g_Wt2hi);
    cudaGetSymbolAddress((void**)&wt2l, g_Wt2lo);

    // CSR (shared by both layers) + ce precompute + W conversion
    zero_counts_kernel<<<(NN + 255) / 256, 256>>>();
    hist_kernel<<<(NE + 255) / 256, 256>>>(dst);
    scan_kernel<<<1, 1024>>>(We1, ae1, We2, ae2);
    scatter_kernel<<<(NE + 255) / 256, 256>>>(dst);
    convert_w_kernel<<<(128 * 256 + 255) / 256, 256>>>(W1, 128, wt1h, wt1l);
    convert_w_kernel<<<(256 * 256 + 255) / 256, 256>>>(W2, 256, wt2h, wt2l);

    run_layer(x, 128, wt1h, wt1l, asrc1, adst1, ce1, b1,
              src, dst, edge_attr, edge_atten, hbuf, out_w1);
    run_layer(hbuf, 256, wt2h, wt2l, asrc2, adst2, ce2, b2,
              src, dst, edge_attr, edge_atten, out_h, out_w2);
}

// round 6
// speedup vs baseline: 2.5008x; 1.0986x over previous
#include <cuda_runtime.h>
#include <cuda_bf16.h>
#include <math.h>
#include <stdint.h>

#define NN 20000
#define NE 640000
#define HD 4
#define CC 64
#define FO 256
#define NEG_SLOPE 0.2f

// ================= scratch =================
__device__ float g_xh[(size_t)NN * FO];
__device__ float g_h[(size_t)NN * FO];
__device__ float g_alpha_r[(size_t)NE * HD];
__device__ int   g_src_r[NE];
__device__ float g_atten_r[NE];
__device__ float g_asrc[NN * HD];
__device__ float g_adst[NN * HD];
__device__ float g_ce1[HD];
__device__ float g_ce2[HD];
__device__ int   g_cnt[NN];
__device__ int   g_cursor[NN];
__device__ int   g_rowstart[NN + 1];
__device__ int   g_perm[NE];
__device__ __align__(16) __nv_bfloat16 g_Wt1hi[256 * 128];
__device__ __align__(16) __nv_bfloat16 g_Wt1lo[256 * 128];
__device__ __align__(16) __nv_bfloat16 g_Wt2hi[256 * 256];
__device__ __align__(16) __nv_bfloat16 g_Wt2lo[256 * 256];

// ================= CSR build =================
__global__ void zero_counts_kernel() {
    int i = blockIdx.x * blockDim.x + threadIdx.x;
    if (i < NN) { g_cnt[i] = 0; g_cursor[i] = 0; }
}

__global__ void hist_kernel(const int* __restrict__ dst) {
    int e = blockIdx.x * blockDim.x + threadIdx.x;
    if (e < NE) atomicAdd(&g_cnt[dst[e]], 1);
}

__global__ void scan_kernel(const float* __restrict__ We1, const float* __restrict__ ae1,
                            const float* __restrict__ We2, const float* __restrict__ ae2)
{
    int tid = threadIdx.x;
    int w = tid >> 5, lane = tid & 31;
    if (w < 8) {
        const float* We = (w < 4) ? We1 : We2;
        const float* ae = (w < 4) ? ae1 : ae2;
        float* ce = (w < 4) ? g_ce1 : g_ce2;
        int h = w & 3;
        float v = We[h * 64 + lane] * ae[h * 64 + lane]
                + We[h * 64 + lane + 32] * ae[h * 64 + lane + 32];
#pragma unroll
        for (int o = 16; o; o >>= 1) v += __shfl_xor_sync(0xffffffffu, v, o);
        if (lane == 0) ce[h] = v;
    }

    __shared__ int buf[1024];
    __shared__ int carry_s;
    if (tid == 0) { carry_s = 0; g_rowstart[0] = 0; }
    __syncthreads();
    for (int base = 0; base < NN; base += 1024) {
        int i = base + tid;
        int v = (i < NN) ? g_cnt[i] : 0;
        buf[tid] = v;
        __syncthreads();
        for (int off = 1; off < 1024; off <<= 1) {
            int t = (tid >= off) ? buf[tid - off] : 0;
            __syncthreads();
            buf[tid] += t;
            __syncthreads();
        }
        int carry = carry_s;
        if (i < NN) g_rowstart[i + 1] = carry + buf[tid];
        __syncthreads();
        if (tid == 1023) carry_s = carry + buf[1023];
        __syncthreads();
    }
}

__global__ void scatter_kernel(const int* __restrict__ dst) {
    int e = blockIdx.x * blockDim.x + threadIdx.x;
    if (e < NE) {
        int d = dst[e];
        int pos = g_rowstart[d] + atomicAdd(&g_cursor[d], 1);
        g_perm[pos] = e;
    }
}

// ================= W transpose + bf16 split =================
__global__ void convert_w_kernel(const float* __restrict__ W, int K,
                                 __nv_bfloat16* __restrict__ Whi,
                                 __nv_bfloat16* __restrict__ Wlo)
{
    int idx = blockIdx.x * blockDim.x + threadIdx.x;
    if (idx >= K * 256) return;
    int k = idx >> 8, n = idx & 255;
    float v = W[idx];
    __nv_bfloat16 h = __float2bfloat16_rn(v);
    float r = v - __bfloat162float(h);
    Whi[n * K + k] = h;
    Wlo[n * K + k] = __float2bfloat16_rn(r);
}

// ================= split-bf16 mma.sync GEMM =================
__device__ __forceinline__ void mma_bf16(float* c, uint32_t a0, uint32_t a1,
                                         uint32_t a2, uint32_t a3,
                                         uint32_t b0, uint32_t b1)
{
    asm volatile(
        "mma.sync.aligned.m16n8k16.row.col.f32.bf16.bf16.f32 "
        "{%0,%1,%2,%3}, {%4,%5,%6,%7}, {%8,%9}, {%0,%1,%2,%3};"
        : "+f"(c[0]), "+f"(c[1]), "+f"(c[2]), "+f"(c[3])
        : "r"(a0), "r"(a1), "r"(a2), "r"(a3), "r"(b0), "r"(b1));
}

#define KP 20  // uint32 pitch per 32-k row (16 data + 4 pad; 80B rows)

__global__ __launch_bounds__(256) void gemm_mma_kernel(
    const float* __restrict__ A,
    const __nv_bfloat16* __restrict__ Bhi,
    const __nv_bfloat16* __restrict__ Blo,
    float* __restrict__ C, int K)
{
    __shared__ uint32_t As_hi[128][KP];
    __shared__ uint32_t As_lo[128][KP];
    __shared__ uint32_t Bs_hi[128][KP];
    __shared__ uint32_t Bs_lo[128][KP];

    int tid = threadIdx.x;
    int wid = tid >> 5, lane = tid & 31;
    int m0c = blockIdx.x * 128, n0c = blockIdx.y * 128;
    int wm0 = (wid >> 1) * 32, wn0 = (wid & 1) * 64;
    int lq = lane >> 2, lr = lane & 3;

    float acc[2][8][4];
#pragma unroll
    for (int mt = 0; mt < 2; mt++)
#pragma unroll
        for (int nt = 0; nt < 8; nt++)
#pragma unroll
            for (int j = 0; j < 4; j++) acc[mt][nt][j] = 0.f;

    int a_row = tid >> 1, a_half = tid & 1;
    int a_grow = m0c + a_row;
    bool a_ok = (a_grow < NN);
    int b_row = tid & 127, b_half = tid >> 7;

    const float* Abase = A + (size_t)a_grow * K + a_half * 16;
    const __nv_bfloat16* Bhbase = Bhi + (size_t)(n0c + b_row) * K + b_half * 16;
    const __nv_bfloat16* Blbase = Blo + (size_t)(n0c + b_row) * K + b_half * 16;

    // prefetch chunk 0 into regs
    float4 av[4];
    uint4 bvh0, bvh1, bvl0, bvl1;
#pragma unroll
    for (int j = 0; j < 4; j++)
        av[j] = a_ok ? *(const float4*)(Abase + j * 4)
                     : make_float4(0.f, 0.f, 0.f, 0.f);
    bvh0 = *(const uint4*)(Bhbase);
    bvh1 = *(const uint4*)(Bhbase + 8);
    bvl0 = *(const uint4*)(Blbase);
    bvl1 = *(const uint4*)(Blbase + 8);

    int nchunks = K >> 5;
    for (int c = 0; c < nchunks; c++) {
        // stage regs -> smem (A converted to hi/lo)
#pragma unroll
        for (int j = 0; j < 4; j++) {
            float4 v = av[j];
            __nv_bfloat162 h01 = __floats2bfloat162_rn(v.x, v.y);
            __nv_bfloat162 h23 = __floats2bfloat162_rn(v.z, v.w);
            __nv_bfloat162 l01 = __floats2bfloat162_rn(v.x - __low2float(h01),
                                                       v.y - __high2float(h01));
            __nv_bfloat162 l23 = __floats2bfloat162_rn(v.z - __low2float(h23),
                                                       v.w - __high2float(h23));
            int ci = (a_half * 16 + j * 4) >> 1;
            As_hi[a_row][ci]     = *(uint32_t*)&h01;
            As_hi[a_row][ci + 1] = *(uint32_t*)&h23;
            As_lo[a_row][ci]     = *(uint32_t*)&l01;
            As_lo[a_row][ci + 1] = *(uint32_t*)&l23;
        }
        {
            int ci = b_half * 8;
            *(uint4*)&Bs_hi[b_row][ci]     = bvh0;
            *(uint4*)&Bs_hi[b_row][ci + 4] = bvh1;
            *(uint4*)&Bs_lo[b_row][ci]     = bvl0;
            *(uint4*)&Bs_lo[b_row][ci + 4] = bvl1;
        }
        __syncthreads();

        // prefetch next chunk while computing
        if (c + 1 < nchunks) {
            int k0 = (c + 1) << 5;
#pragma unroll
            for (int j = 0; j < 4; j++)
                av[j] = a_ok ? *(const float4*)(Abase + k0 + j * 4)
                             : make_float4(0.f, 0.f, 0.f, 0.f);
            bvh0 = *(const uint4*)(Bhbase + k0);
            bvh1 = *(const uint4*)(Bhbase + k0 + 8);
            bvl0 = *(const uint4*)(Blbase + k0);
            bvl1 = *(const uint4*)(Blbase + k0 + 8);
        }

#pragma unroll
        for (int ks = 0; ks < 2; ks++) {
            int kb = ks * 8 + lr;
            uint32_t ah[2][4], al[2][4];
#pragma unroll
            for (int mt = 0; mt < 2; mt++) {
                int ra = wm0 + mt * 16 + lq, rb = ra + 8;
                ah[mt][0] = As_hi[ra][kb];     ah[mt][1] = As_hi[rb][kb];
                ah[mt][2] = As_hi[ra][kb + 4]; ah[mt][3] = As_hi[rb][kb + 4];
                al[mt][0] = As_lo[ra][kb];     al[mt][1] = As_lo[rb][kb];
                al[mt][2] = As_lo[ra][kb + 4]; al[mt][3] = As_lo[rb][kb + 4];
            }
#pragma unroll
            for (int nt = 0; nt < 8; nt++) {
                int nr = wn0 + nt * 8 + lq;
                uint32_t bh0 = Bs_hi[nr][kb], bh1 = Bs_hi[nr][kb + 4];
                uint32_t bl0 = Bs_lo[nr][kb], bl1 = Bs_lo[nr][kb + 4];
#pragma unroll
                for (int mt = 0; mt < 2; mt++) {
                    mma_bf16(acc[mt][nt], ah[mt][0], ah[mt][1], ah[mt][2], ah[mt][3], bh0, bh1);
                    mma_bf16(acc[mt][nt], ah[mt][0], ah[mt][1], ah[mt][2], ah[mt][3], bl0, bl1);
                    mma_bf16(acc[mt][nt], al[mt][0], al[mt][1], al[mt][2], al[mt][3], bh0, bh1);
                }
            }
        }
        __syncthreads();
    }

#pragma unroll
    for (int mt = 0; mt < 2; mt++) {
        int row0 = m0c + wm0 + mt * 16 + lq;
#pragma unroll
        for (int nt = 0; nt < 8; nt++) {
            int col = n0c + wn0 + nt * 8 + 2 * lr;
            if (row0 < NN)
                *(float2*)(C + (size_t)row0 * FO + col) =
                    make_float2(acc[mt][nt][0], acc[mt][nt][1]);
            if (row0 + 8 < NN)
                *(float2*)(C + (size_t)(row0 + 8) * FO + col) =
                    make_float2(acc[mt][nt][2], acc[mt][nt][3]);
        }
    }
}

// ================= per-node attention dots =================
__global__ __launch_bounds__(256) void node_alpha_kernel(
    const float* __restrict__ asrc, const float* __restrict__ adst)
{
    int task = blockIdx.x * 8 + (threadIdx.x >> 5);
    int lane = threadIdx.x & 31;
    if (task >= NN * HD) return;
    int n = task >> 2, h = task & 3;
    const float* xr = g_xh + (size_t)n * FO + h * 64;
    float v0 = xr[lane], v1 = xr[lane + 32];
    float s = v0 * asrc[h * 64 + lane] + v1 * asrc[h * 64 + lane + 32];
    float d = v0 * adst[h * 64 + lane] + v1 * adst[h * 64 + lane + 32];
#pragma unroll
    for (int o = 16; o; o >>= 1) {
        s += __shfl_xor_sync(0xffffffffu, s, o);
        d += __shfl_xor_sync(0xffffffffu, d, o);
    }
    if (lane == 0) { g_asrc[n * 4 + h] = s; g_adst[n * 4 + h] = d; }
}

// ================= fused: logits + softmax + gather, warp per dst =================
__global__ __launch_bounds__(256) void fused_agg_kernel(
    const int* __restrict__ src,
    const float* __restrict__ edge_attr,
    const float* __restrict__ edge_atten,
    const float* __restrict__ ce,
    const float* __restrict__ bias,
    float* __restrict__ out_h,
    float* __restrict__ out_w)
{
    __shared__ float s_w[8][32][4];
    __shared__ int   s_s[8][32];
    int wslot = threadIdx.x >> 5;
    int n = blockIdx.x * 8 + wslot;
    int lane = threadIdx.x & 31;
    if (n >= NN) return;
    int r0 = g_rowstart[n], r1 = g_rowstart[n + 1];

    float4 c   = *(const float4*)ce;
    float4 adn = *(const float4*)(g_adst + (size_t)n * 4);  // dst == n, warp-uniform

    // ---- pass 1: logits + leaky relu + max ----
    float mx0 = -3.4e38f, mx1 = -3.4e38f, mx2 = -3.4e38f, mx3 = -3.4e38f;
    for (int i = r0 + lane; i < r1; i += 32) {
        int e = g_perm[i];
        int s = src[e];
        float ea = edge_attr[e];
        float at = edge_atten[e];
        float4 as = *(const float4*)(g_asrc + (size_t)s * 4);
        float a0 = as.x + adn.x + ea * c.x;
        float a1 = as.y + adn.y + ea * c.y;
        float a2 = as.z + adn.z + ea * c.z;
        float a3 = as.w + adn.w + ea * c.w;
        a0 = a0 > 0.f ? a0 : NEG_SLOPE * a0;
        a1 = a1 > 0.f ? a1 : NEG_SLOPE * a1;
        a2 = a2 > 0.f ? a2 : NEG_SLOPE * a2;
        a3 = a3 > 0.f ? a3 : NEG_SLOPE * a3;
        *(float4*)(g_alpha_r + (size_t)i * 4) = make_float4(a0, a1, a2, a3);
        g_src_r[i] = s;
        g_atten_r[i] = at;
        mx0 = fmaxf(mx0, a0); mx1 = fmaxf(mx1, a1);
        mx2 = fmaxf(mx2, a2); mx3 = fmaxf(mx3, a3);
    }
#pragma unroll
    for (int o = 16; o; o >>= 1) {
        mx0 = fmaxf(mx0, __shfl_xor_sync(0xffffffffu, mx0, o));
        mx1 = fmaxf(mx1, __shfl_xor_sync(0xffffffffu, mx1, o));
        mx2 = fmaxf(mx2, __shfl_xor_sync(0xffffffffu, mx2, o));
        mx3 = fmaxf(mx3, __shfl_xor_sync(0xffffffffu, mx3, o));
    }

    // ---- pass 2: denom ----
    float dn0 = 0.f, dn1 = 0.f, dn2 = 0.f, dn3 = 0.f;
    for (int i = r0 + lane; i < r1; i += 32) {
        float4 a = *(const float4*)(g_alpha_r + (size_t)i * 4);
        dn0 += __expf(a.x - mx0); dn1 += __expf(a.y - mx1);
        dn2 += __expf(a.z - mx2); dn3 += __expf(a.w - mx3);
    }
#pragma unroll
    for (int o = 16; o; o >>= 1) {
        dn0 += __shfl_xor_sync(0xffffffffu, dn0, o);
        dn1 += __shfl_xor_sync(0xffffffffu, dn1, o);
        dn2 += __shfl_xor_sync(0xffffffffu, dn2, o);
        dn3 += __shfl_xor_sync(0xffffffffu, dn3, o);
    }
    float inv0 = 1.f / (dn0 + 1e-16f);
    float inv1 = 1.f / (dn1 + 1e-16f);
    float inv2 = 1.f / (dn2 + 1e-16f);
    float inv3 = 1.f / (dn3 + 1e-16f);

    // ---- pass 3: weights (lane-parallel) + staged serial gather ----
    bool hi = lane >= 16;
    float4 accA = make_float4(0.f, 0.f, 0.f, 0.f);
    float4 accB = make_float4(0.f, 0.f, 0.f, 0.f);

    for (int base = r0; base < r1; base += 32) {
        int i = base + lane;
        int cnt = min(32, r1 - base);
        if (i < r1) {
            float4 a = *(const float4*)(g_alpha_r + (size_t)i * 4);
            float w0 = __expf(a.x - mx0) * inv0;
            float w1 = __expf(a.y - mx1) * inv1;
            float w2 = __expf(a.z - mx2) * inv2;
            float w3 = __expf(a.w - mx3) * inv3;
            int e = g_perm[i];
            *(float4*)(out_w + (size_t)e * 4) = make_float4(w0, w1, w2, w3);
            float at = g_atten_r[i];
            *(float4*)&s_w[wslot][lane][0] = make_float4(w0 * at, w1 * at, w2 * at, w3 * at);
            s_s[wslot][lane] = g_src_r[i];
        }
        __syncwarp();
        for (int j = 0; j < cnt; j++) {
            float4 w4 = *(const float4*)&s_w[wslot][j][0];
            int sc = s_s[wslot][j];
            float wA = hi ? w4.y : w4.x;
            float wB = hi ? w4.w : w4.z;
            const float* xr = g_xh + (size_t)sc * FO;
            float4 vA = *(const float4*)(xr + lane * 4);
            float4 vB = *(const float4*)(xr + 128 + lane * 4);
            accA.x += wA * vA.x; accA.y += wA * vA.y;
            accA.z += wA * vA.z; accA.w += wA * vA.w;
            accB.x += wB * vB.x; accB.y += wB * vB.y;
            accB.z += wB * vB.z; accB.w += wB * vB.w;
        }
        __syncwarp();
    }

    float4 bA = *(const float4*)(bias + lane * 4);
    float4 bB = *(const float4*)(bias + 128 + lane * 4);
    float* orow = out_h + (size_t)n * FO;
    *(float4*)(orow + lane * 4) =
        make_float4(accA.x + bA.x, accA.y + bA.y, accA.z + bA.z, accA.w + bA.w);
    *(float4*)(orow + 128 + lane * 4) =
        make_float4(accB.x + bB.x, accB.y + bB.y, accB.z + bB.z, accB.w + bB.w);
}

// ================= launch =================
static void run_layer(const float* xin, int Kdim,
                      const __nv_bfloat16* Whi, const __nv_bfloat16* Wlo,
                      const float* asrc, const float* adst,
                      const float* ce_dev, const float* b,
                      const int* src,
                      const float* edge_attr, const float* edge_atten,
                      float* out_h, float* out_w)
{
    float* xh;
    cudaGetSymbolAddress((void**)&xh, g_xh);
    dim3 ggrid((NN + 127) / 128, 2);
    gemm_mma_kernel<<<ggrid, 256>>>(xin, Whi, Wlo, xh, Kdim);
    node_alpha_kernel<<<(NN * HD + 7) / 8, 256>>>(asrc, adst);
    fused_agg_kernel<<<(NN + 7) / 8, 256>>>(src, edge_attr, edge_atten, ce_dev, b,
                                            out_h, out_w);
}

extern "C" void kernel_launch(void* const* d_in, const int* in_sizes, int n_in,
                              void* d_out, int out_size)
{
    const float* x          = (const float*)d_in[0];
    const int*   edge_index = (const int*)d_in[1];
    const float* edge_attr  = (const float*)d_in[3];
    const float* edge_atten = (const float*)d_in[4];
    const float* W1    = (const float*)d_in[5];
    const float* asrc1 = (const float*)d_in[6];
    const float* adst1 = (const float*)d_in[7];
    const float* We1   = (const float*)d_in[8];
    const float* ae1   = (const float*)d_in[9];
    const float* b1    = (const float*)d_in[10];
    const float* W2    = (const float*)d_in[11];
    const float* asrc2 = (const float*)d_in[12];
    const float* adst2 = (const float*)d_in[13];
    const float* We2   = (const float*)d_in[14];
    const float* ae2   = (const float*)d_in[15];
    const float* b2    = (const float*)d_in[16];

    const int* src = edge_index;
    const int* dst = edge_index + NE;

    float* out    = (float*)d_out;
    float* out_h  = out;
    float* out_w1 = out + (size_t)NN * FO;
    float* out_w2 = out_w1 + (size_t)NE * HD;

    float* hbuf; cudaGetSymbolAddress((void**)&hbuf, g_h);
    float* ce1;  cudaGetSymbolAddress((void**)&ce1, g_ce1);
    float* ce2;  cudaGetSymbolAddress((void**)&ce2, g_ce2);
    __nv_bfloat16 *wt1h, *wt1l, *wt2h, *wt2l;
    cudaGetSymbolAddress((void**)&wt1h, g_Wt1hi);
    cudaGetSymbolAddress((void**)&wt1l, g_Wt1lo);
    cudaGetSymbolAddress((void**)&wt2h, g_Wt2hi);
    cudaGetSymbolAddress((void**)&wt2l, g_Wt2lo);

    // CSR (shared by both layers) + ce precompute + W conversion
    zero_counts_kernel<<<(NN + 255) / 256, 256>>>();
    hist_kernel<<<(NE + 255) / 256, 256>>>(dst);
    scan_kernel<<<1, 1024>>>(We1, ae1, We2, ae2);
    scatter_kernel<<<(NE + 255) / 256, 256>>>(dst);
    convert_w_kernel<<<(128 * 256 + 255) / 256, 256>>>(W1, 128, wt1h, wt1l);
    convert_w_kernel<<<(256 * 256 + 255) / 256, 256>>>(W2, 256, wt2h, wt2l);

    run_layer(x, 128, wt1h, wt1l, asrc1, adst1, ce1, b1,
              src, edge_attr, edge_atten, hbuf, out_w1);
    run_layer(hbuf, 256, wt2h, wt2l, asrc2, adst2, ce2, b2,
              src, edge_attr, edge_atten, out_h, out_w2);
}

// round 7
// speedup vs baseline: 3.0893x; 1.2353x over previous
#include <cuda_runtime.h>
#include <cuda_bf16.h>
#include <math.h>
#include <stdint.h>

#define NN 20000
#define NE 640000
#define HD 4
#define CC 64
#define FO 256
#define NEG_SLOPE 0.2f

struct __align__(16) EdgeRec { int e; int s; float ea; float at; };

// ================= scratch =================
__device__ float g_xh[(size_t)NN * FO];
__device__ float g_h[(size_t)NN * FO];
__device__ float g_alpha_r[(size_t)NE * HD];   // logits, then exp values (in-place)
__device__ EdgeRec g_edge_r[NE];
__device__ float g_asrc[NN * HD];
__device__ float g_adst[NN * HD];
__device__ float g_ce1[HD];
__device__ float g_ce2[HD];
__device__ int   g_cnt[NN];
__device__ int   g_cursor[NN];
__device__ int   g_rowstart[NN + 1];
__device__ __align__(16) __nv_bfloat16 g_Wt1hi[256 * 128];
__device__ __align__(16) __nv_bfloat16 g_Wt1lo[256 * 128];
__device__ __align__(16) __nv_bfloat16 g_Wt2hi[256 * 256];
__device__ __align__(16) __nv_bfloat16 g_Wt2lo[256 * 256];

// ================= CSR build =================
__global__ void zero_counts_kernel() {
    int i = blockIdx.x * blockDim.x + threadIdx.x;
    if (i < NN) { g_cnt[i] = 0; g_cursor[i] = 0; }
}

__global__ void hist_kernel(const int* __restrict__ dst) {
    int e = (blockIdx.x * blockDim.x + threadIdx.x) * 4;
    if (e + 3 < NE) {
        int4 d = *(const int4*)(dst + e);
        atomicAdd(&g_cnt[d.x], 1);
        atomicAdd(&g_cnt[d.y], 1);
        atomicAdd(&g_cnt[d.z], 1);
        atomicAdd(&g_cnt[d.w], 1);
    } else {
        for (int j = e; j < NE; j++) atomicAdd(&g_cnt[j - e + e], 1), j = NE; // unreachable for NE%4==0
    }
}

// single-pass scan (1024 threads, 20 nodes/thread) + fused ce precompute
__global__ void scan_kernel(const float* __restrict__ We1, const float* __restrict__ ae1,
                            const float* __restrict__ We2, const float* __restrict__ ae2)
{
    int tid = threadIdx.x;
    int wq = tid >> 5, lane = tid & 31;
    if (wq < 8) {
        const float* We = (wq < 4) ? We1 : We2;
        const float* ae = (wq < 4) ? ae1 : ae2;
        float* ce = (wq < 4) ? g_ce1 : g_ce2;
        int h = wq & 3;
        float v = We[h * 64 + lane] * ae[h * 64 + lane]
                + We[h * 64 + lane + 32] * ae[h * 64 + lane + 32];
#pragma unroll
        for (int o = 16; o; o >>= 1) v += __shfl_xor_sync(0xffffffffu, v, o);
        if (lane == 0) ce[h] = v;
    }

    const int PER = 20;  // 1024*20 >= 20000
    int base = tid * PER;
    int loc[PER];
    int sum = 0;
#pragma unroll
    for (int j = 0; j < PER; j++) {
        int i = base + j;
        int v = (i < NN) ? g_cnt[i] : 0;
        sum += v;
        loc[j] = sum;            // inclusive within thread
    }
    // block exclusive scan of per-thread sums
    int x = sum;
#pragma unroll
    for (int o = 1; o < 32; o <<= 1) {
        int t = __shfl_up_sync(0xffffffffu, x, o);
        if (lane >= o) x += t;
    }
    __shared__ int wsum[32];
    if (lane == 31) wsum[wq] = x;
    __syncthreads();
    if (wq == 0) {
        int y = (lane < 32) ? wsum[lane] : 0;
#pragma unroll
        for (int o = 1; o < 32; o <<= 1) {
            int t = __shfl_up_sync(0xffffffffu, y, o);
            if (lane >= o) y += t;
        }
        wsum[lane] = y;
    }
    __syncthreads();
    int excl = x - sum + (wq ? wsum[wq - 1] : 0);
    if (tid == 0) g_rowstart[0] = 0;
#pragma unroll
    for (int j = 0; j < PER; j++) {
        int i = base + j;
        if (i < NN) g_rowstart[i + 1] = excl + loc[j];
    }
}

// scatter: build CSR-ordered EdgeRec stream (coalesced reads, one 16B random write)
__global__ void scatter_kernel(const int* __restrict__ src,
                               const int* __restrict__ dst,
                               const float* __restrict__ edge_attr,
                               const float* __restrict__ edge_atten)
{
    int e = (blockIdx.x * blockDim.x + threadIdx.x) * 2;
    if (e + 1 < NE) {
        int2   d2 = *(const int2*)(dst + e);
        int2   s2 = *(const int2*)(src + e);
        float2 ea = *(const float2*)(edge_attr + e);
        float2 at = *(const float2*)(edge_atten + e);
        int p0 = g_rowstart[d2.x] + atomicAdd(&g_cursor[d2.x], 1);
        int p1 = g_rowstart[d2.y] + atomicAdd(&g_cursor[d2.y], 1);
        EdgeRec r0 = {e, s2.x, ea.x, at.x};
        EdgeRec r1 = {e + 1, s2.y, ea.y, at.y};
        g_edge_r[p0] = r0;
        g_edge_r[p1] = r1;
    }
}

// ================= W transpose + bf16 split (both layers, one launch) =======
__global__ void convert_w_kernel(const float* __restrict__ W1,
                                 const float* __restrict__ W2,
                                 __nv_bfloat16* __restrict__ W1hi,
                                 __nv_bfloat16* __restrict__ W1lo,
                                 __nv_bfloat16* __restrict__ W2hi,
                                 __nv_bfloat16* __restrict__ W2lo)
{
    int idx = blockIdx.x * blockDim.x + threadIdx.x;
    if (idx < 128 * 256) {
        int k = idx >> 8, n = idx & 255;
        float v = W1[idx];
        __nv_bfloat16 h = __float2bfloat16_rn(v);
        W1hi[n * 128 + k] = h;
        W1lo[n * 128 + k] = __float2bfloat16_rn(v - __bfloat162float(h));
    } else if (idx < 128 * 256 + 256 * 256) {
        int i2 = idx - 128 * 256;
        int k = i2 >> 8, n = i2 & 255;
        float v = W2[i2];
        __nv_bfloat16 h = __float2bfloat16_rn(v);
        W2hi[n * 256 + k] = h;
        W2lo[n * 256 + k] = __float2bfloat16_rn(v - __bfloat162float(h));
    }
}

// ================= split-bf16 mma.sync GEMM + fused alpha dots =================
__device__ __forceinline__ void mma_bf16(float* c, uint32_t a0, uint32_t a1,
                                         uint32_t a2, uint32_t a3,
                                         uint32_t b0, uint32_t b1)
{
    asm volatile(
        "mma.sync.aligned.m16n8k16.row.col.f32.bf16.bf16.f32 "
        "{%0,%1,%2,%3}, {%4,%5,%6,%7}, {%8,%9}, {%0,%1,%2,%3};"
        : "+f"(c[0]), "+f"(c[1]), "+f"(c[2]), "+f"(c[3])
        : "r"(a0), "r"(a1), "r"(a2), "r"(a3), "r"(b0), "r"(b1));
}

#define KP 20  // uint32 pitch per 32-k row (80B rows, 16B-aligned)

__global__ __launch_bounds__(256) void gemm_mma_kernel(
    const float* __restrict__ A,
    const __nv_bfloat16* __restrict__ Bhi,
    const __nv_bfloat16* __restrict__ Blo,
    float* __restrict__ C, int K,
    const float* __restrict__ asrc, const float* __restrict__ adst)
{
    __shared__ uint32_t As_hi[128][KP];
    __shared__ uint32_t As_lo[128][KP];
    __shared__ uint32_t Bs_hi[128][KP];
    __shared__ uint32_t Bs_lo[128][KP];

    int tid = threadIdx.x;
    int wid = tid >> 5, lane = tid & 31;
    int m0c = blockIdx.x * 128, n0c = blockIdx.y * 128;
    int wm0 = (wid >> 1) * 32, wn0 = (wid & 1) * 64;
    int lq = lane >> 2, lr = lane & 3;

    float acc[2][8][4];
#pragma unroll
    for (int mt = 0; mt < 2; mt++)
#pragma unroll
        for (int nt = 0; nt < 8; nt++)
#pragma unroll
            for (int j = 0; j < 4; j++) acc[mt][nt][j] = 0.f;

    int a_row = tid >> 1, a_half = tid & 1;
    int a_grow = m0c + a_row;
    bool a_ok = (a_grow < NN);
    int b_row = tid & 127, b_half = tid >> 7;

    const float* Abase = A + (size_t)a_grow * K + a_half * 16;
    const __nv_bfloat16* Bhbase = Bhi + (size_t)(n0c + b_row) * K + b_half * 16;
    const __nv_bfloat16* Blbase = Blo + (size_t)(n0c + b_row) * K + b_half * 16;

    float4 av[4];
    uint4 bvh0, bvh1, bvl0, bvl1;
#pragma unroll
    for (int j = 0; j < 4; j++)
        av[j] = a_ok ? *(const float4*)(Abase + j * 4)
                     : make_float4(0.f, 0.f, 0.f, 0.f);
    bvh0 = *(const uint4*)(Bhbase);
    bvh1 = *(const uint4*)(Bhbase + 8);
    bvl0 = *(const uint4*)(Blbase);
    bvl1 = *(const uint4*)(Blbase + 8);

    int nchunks = K >> 5;
    for (int c = 0; c < nchunks; c++) {
#pragma unroll
        for (int j = 0; j < 4; j++) {
            float4 v = av[j];
            __nv_bfloat162 h01 = __floats2bfloat162_rn(v.x, v.y);
            __nv_bfloat162 h23 = __floats2bfloat162_rn(v.z, v.w);
            __nv_bfloat162 l01 = __floats2bfloat162_rn(v.x - __low2float(h01),
                                                       v.y - __high2float(h01));
            __nv_bfloat162 l23 = __floats2bfloat162_rn(v.z - __low2float(h23),
                                                       v.w - __high2float(h23));
            int ci = (a_half * 16 + j * 4) >> 1;
            As_hi[a_row][ci]     = *(uint32_t*)&h01;
            As_hi[a_row][ci + 1] = *(uint32_t*)&h23;
            As_lo[a_row][ci]     = *(uint32_t*)&l01;
            As_lo[a_row][ci + 1] = *(uint32_t*)&l23;
        }
        {
            int ci = b_half * 8;
            *(uint4*)&Bs_hi[b_row][ci]     = bvh0;
            *(uint4*)&Bs_hi[b_row][ci + 4] = bvh1;
            *(uint4*)&Bs_lo[b_row][ci]     = bvl0;
            *(uint4*)&Bs_lo[b_row][ci + 4] = bvl1;
        }
        __syncthreads();

        if (c + 1 < nchunks) {
            int k0 = (c + 1) << 5;
#pragma unroll
            for (int j = 0; j < 4; j++)
                av[j] = a_ok ? *(const float4*)(Abase + k0 + j * 4)
                             : make_float4(0.f, 0.f, 0.f, 0.f);
            bvh0 = *(const uint4*)(Bhbase + k0);
            bvh1 = *(const uint4*)(Bhbase + k0 + 8);
            bvl0 = *(const uint4*)(Blbase + k0);
            bvl1 = *(const uint4*)(Blbase + k0 + 8);
        }

#pragma unroll
        for (int ks = 0; ks < 2; ks++) {
            int kb = ks * 8 + lr;
            uint32_t ah[2][4], al[2][4];
#pragma unroll
            for (int mt = 0; mt < 2; mt++) {
                int ra = wm0 + mt * 16 + lq, rb = ra + 8;
                ah[mt][0] = As_hi[ra][kb];     ah[mt][1] = As_hi[rb][kb];
                ah[mt][2] = As_hi[ra][kb + 4]; ah[mt][3] = As_hi[rb][kb + 4];
                al[mt][0] = As_lo[ra][kb];     al[mt][1] = As_lo[rb][kb];
                al[mt][2] = As_lo[ra][kb + 4]; al[mt][3] = As_lo[rb][kb + 4];
            }
#pragma unroll
            for (int nt = 0; nt < 8; nt++) {
                int nr = wn0 + nt * 8 + lq;
                uint32_t bh0 = Bs_hi[nr][kb], bh1 = Bs_hi[nr][kb + 4];
                uint32_t bl0 = Bs_lo[nr][kb], bl1 = Bs_lo[nr][kb + 4];
#pragma unroll
                for (int mt = 0; mt < 2; mt++) {
                    mma_bf16(acc[mt][nt], ah[mt][0], ah[mt][1], ah[mt][2], ah[mt][3], bh0, bh1);
                    mma_bf16(acc[mt][nt], ah[mt][0], ah[mt][1], ah[mt][2], ah[mt][3], bl0, bl1);
                    mma_bf16(acc[mt][nt], al[mt][0], al[mt][1], al[mt][2], al[mt][3], bh0, bh1);
                }
            }
        }
        __syncthreads();
    }

    // ---- C store ----
#pragma unroll
    for (int mt = 0; mt < 2; mt++) {
        int row0 = m0c + wm0 + mt * 16 + lq;
#pragma unroll
        for (int nt = 0; nt < 8; nt++) {
            int col = n0c + wn0 + nt * 8 + 2 * lr;
            if (row0 < NN)
                *(float2*)(C + (size_t)row0 * FO + col) =
                    make_float2(acc[mt][nt][0], acc[mt][nt][1]);
            if (row0 + 8 < NN)
                *(float2*)(C + (size_t)(row0 + 8) * FO + col) =
                    make_float2(acc[mt][nt][2], acc[mt][nt][3]);
        }
    }

    // ---- fused alpha_src / alpha_dst (this warp's tile = one head's 64 cols) ----
    {
        int h = (n0c + wn0) >> 6;
        float ps0 = 0.f, ps1 = 0.f, ps2 = 0.f, ps3 = 0.f;
        float pd0 = 0.f, pd1 = 0.f, pd2 = 0.f, pd3 = 0.f;
#pragma unroll
        for (int nt = 0; nt < 8; nt++) {
            int c0 = nt * 8 + 2 * lr;
            float2 cs = *(const float2*)(asrc + h * 64 + c0);
            float2 cd = *(const float2*)(adst + h * 64 + c0);
            ps0 += acc[0][nt][0] * cs.x + acc[0][nt][1] * cs.y;
            ps1 += acc[0][nt][2] * cs.x + acc[0][nt][3] * cs.y;
            ps2 += acc[1][nt][0] * cs.x + acc[1][nt][1] * cs.y;
            ps3 += acc[1][nt][2] * cs.x + acc[1][nt][3] * cs.y;
            pd0 += acc[0][nt][0] * cd.x + acc[0][nt][1] * cd.y;
            pd1 += acc[0][nt][2] * cd.x + acc[0][nt][3] * cd.y;
            pd2 += acc[1][nt][0] * cd.x + acc[1][nt][1] * cd.y;
            pd3 += acc[1][nt][2] * cd.x + acc[1][nt][3] * cd.y;
        }
#pragma unroll
        for (int o = 1; o <= 2; o <<= 1) {
            ps0 += __shfl_xor_sync(0xffffffffu, ps0, o);
            ps1 += __shfl_xor_sync(0xffffffffu, ps1, o);
            ps2 += __shfl_xor_sync(0xffffffffu, ps2, o);
            ps3 += __shfl_xor_sync(0xffffffffu, ps3, o);
            pd0 += __shfl_xor_sync(0xffffffffu, pd0, o);
            pd1 += __shfl_xor_sync(0xffffffffu, pd1, o);
            pd2 += __shfl_xor_sync(0xffffffffu, pd2, o);
            pd3 += __shfl_xor_sync(0xffffffffu, pd3, o);
        }
        if (lr == 0) {
            int r = m0c + wm0 + lq;
            if (r < NN)      { g_asrc[r * 4 + h] = ps0;        g_adst[r * 4 + h] = pd0; }
            if (r + 8 < NN)  { g_asrc[(r + 8) * 4 + h] = ps1;  g_adst[(r + 8) * 4 + h] = pd1; }
            if (r + 16 < NN) { g_asrc[(r + 16) * 4 + h] = ps2; g_adst[(r + 16) * 4 + h] = pd2; }
            if (r + 24 < NN) { g_asrc[(r + 24) * 4 + h] = ps3; g_adst[(r + 24) * 4 + h] = pd3; }
        }
    }
}

// ================= fused: logits + softmax + gather, warp per dst =================
__global__ __launch_bounds__(256) void fused_agg_kernel(
    const float* __restrict__ ce,
    const float* __restrict__ bias,
    float* __restrict__ out_h,
    float* __restrict__ out_w)
{
    __shared__ float s_w[8][32][4];
    __shared__ int   s_s[8][32];
    int wslot = threadIdx.x >> 5;
    int n = blockIdx.x * 8 + wslot;
    int lane = threadIdx.x & 31;
    if (n >= NN) return;
    int r0 = g_rowstart[n], r1 = g_rowstart[n + 1];

    float4 c   = *(const float4*)ce;
    float4 adn = *(const float4*)(g_adst + (size_t)n * 4);

    // ---- pass 1: logits + leaky relu + max ----
    float mx0 = -3.4e38f, mx1 = -3.4e38f, mx2 = -3.4e38f, mx3 = -3.4e38f;
    for (int i = r0 + lane; i < r1; i += 32) {
        EdgeRec er = g_edge_r[i];
        float4 as = *(const float4*)(g_asrc + (size_t)er.s * 4);
        float a0 = as.x + adn.x + er.ea * c.x;
        float a1 = as.y + adn.y + er.ea * c.y;
        float a2 = as.z + adn.z + er.ea * c.z;
        float a3 = as.w + adn.w + er.ea * c.w;
        a0 = a0 > 0.f ? a0 : NEG_SLOPE * a0;
        a1 = a1 > 0.f ? a1 : NEG_SLOPE * a1;
        a2 = a2 > 0.f ? a2 : NEG_SLOPE * a2;
        a3 = a3 > 0.f ? a3 : NEG_SLOPE * a3;
        *(float4*)(g_alpha_r + (size_t)i * 4) = make_float4(a0, a1, a2, a3);
        mx0 = fmaxf(mx0, a0); mx1 = fmaxf(mx1, a1);
        mx2 = fmaxf(mx2, a2); mx3 = fmaxf(mx3, a3);
    }
#pragma unroll
    for (int o = 16; o; o >>= 1) {
        mx0 = fmaxf(mx0, __shfl_xor_sync(0xffffffffu, mx0, o));
        mx1 = fmaxf(mx1, __shfl_xor_sync(0xffffffffu, mx1, o));
        mx2 = fmaxf(mx2, __shfl_xor_sync(0xffffffffu, mx2, o));
        mx3 = fmaxf(mx3, __shfl_xor_sync(0xffffffffu, mx3, o));
    }

    // ---- pass 2: exp (stored in place) + denom ----
    float dn0 = 0.f, dn1 = 0.f, dn2 = 0.f, dn3 = 0.f;
    for (int i = r0 + lane; i < r1; i += 32) {
        float4 a = *(const float4*)(g_alpha_r + (size_t)i * 4);
        float e0 = __expf(a.x - mx0), e1 = __expf(a.y - mx1);
        float e2 = __expf(a.z - mx2), e3 = __expf(a.w - mx3);
        *(float4*)(g_alpha_r + (size_t)i * 4) = make_float4(e0, e1, e2, e3);
        dn0 += e0; dn1 += e1; dn2 += e2; dn3 += e3;
    }
#pragma unroll
    for (int o = 16; o; o >>= 1) {
        dn0 += __shfl_xor_sync(0xffffffffu, dn0, o);
        dn1 += __shfl_xor_sync(0xffffffffu, dn1, o);
        dn2 += __shfl_xor_sync(0xffffffffu, dn2, o);
        dn3 += __shfl_xor_sync(0xffffffffu, dn3, o);
    }
    float inv0 = 1.f / (dn0 + 1e-16f);
    float inv1 = 1.f / (dn1 + 1e-16f);
    float inv2 = 1.f / (dn2 + 1e-16f);
    float inv3 = 1.f / (dn3 + 1e-16f);

    // ---- pass 3: weights (no exp) + staged serial gather ----
    bool hi = lane >= 16;
    float4 accA = make_float4(0.f, 0.f, 0.f, 0.f);
    float4 accB = make_float4(0.f, 0.f, 0.f, 0.f);

    for (int base = r0; base < r1; base += 32) {
        int i = base + lane;
        int cnt = min(32, r1 - base);
        if (i < r1) {
            float4 ex = *(const float4*)(g_alpha_r + (size_t)i * 4);
            EdgeRec er = g_edge_r[i];
            float w0 = ex.x * inv0, w1 = ex.y * inv1;
            float w2 = ex.z * inv2, w3 = ex.w * inv3;
            *(float4*)(out_w + (size_t)er.e * 4) = make_float4(w0, w1, w2, w3);
            *(float4*)&s_w[wslot][lane][0] =
                make_float4(w0 * er.at, w1 * er.at, w2 * er.at, w3 * er.at);
            s_s[wslot][lane] = er.s;
        }
        __syncwarp();
        for (int j = 0; j < cnt; j++) {
            float4 w4 = *(const float4*)&s_w[wslot][j][0];
            int sc = s_s[wslot][j];
            float wA = hi ? w4.y : w4.x;
            float wB = hi ? w4.w : w4.z;
            const float* xr = g_xh + (size_t)sc * FO;
            float4 vA = *(const float4*)(xr + lane * 4);
            float4 vB = *(const float4*)(xr + 128 + lane * 4);
            accA.x += wA * vA.x; accA.y += wA * vA.y;
            accA.z += wA * vA.z; accA.w += wA * vA.w;
            accB.x += wB * vB.x; accB.y += wB * vB.y;
            accB.z += wB * vB.z; accB.w += wB * vB.w;
        }
        __syncwarp();
    }

    float4 bA = *(const float4*)(bias + lane * 4);
    float4 bB = *(const float4*)(bias + 128 + lane * 4);
    float* orow = out_h + (size_t)n * FO;
    *(float4*)(orow + lane * 4) =
        make_float4(accA.x + bA.x, accA.y + bA.y, accA.z + bA.z, accA.w + bA.w);
    *(float4*)(orow + 128 + lane * 4) =
        make_float4(accB.x + bB.x, accB.y + bB.y, accB.z + bB.z, accB.w + bB.w);
}

// ================= launch =================
static void run_layer(const float* xin, int Kdim,
                      const __nv_bfloat16* Whi, const __nv_bfloat16* Wlo,
                      const float* asrc, const float* adst,
                      const float* ce_dev, const float* b,
                      float* out_h, float* out_w)
{
    float* xh;
    cudaGetSymbolAddress((void**)&xh, g_xh);
    dim3 ggrid((NN + 127) / 128, 2);
    gemm_mma_kernel<<<ggrid, 256>>>(xin, Whi, Wlo, xh, Kdim, asrc, adst);
    fused_agg_kernel<<<(NN + 7) / 8, 256>>>(ce_dev, b, out_h, out_w);
}

extern "C" void kernel_launch(void* const* d_in, const int* in_sizes, int n_in,
                              void* d_out, int out_size)
{
    const float* x          = (const float*)d_in[0];
    const int*   edge_index = (const int*)d_in[1];
    const float* edge_attr  = (const float*)d_in[3];
    const float* edge_atten = (const float*)d_in[4];
    const float* W1    = (const float*)d_in[5];
    const float* asrc1 = (const float*)d_in[6];
    const float* adst1 = (const float*)d_in[7];
    const float* We1   = (const float*)d_in[8];
    const float* ae1   = (const float*)d_in[9];
    const float* b1    = (const float*)d_in[10];
    const float* W2    = (const float*)d_in[11];
    const float* asrc2 = (const float*)d_in[12];
    const float* adst2 = (const float*)d_in[13];
    const float* We2   = (const float*)d_in[14];
    const float* ae2   = (const float*)d_in[15];
    const float* b2    = (const float*)d_in[16];

    const int* src = edge_index;
    const int* dst = edge_index + NE;

    float* out    = (float*)d_out;
    float* out_h  = out;
    float* out_w1 = out + (size_t)NN * FO;
    float* out_w2 = out_w1 + (size_t)NE * HD;

    float* hbuf; cudaGetSymbolAddress((void**)&hbuf, g_h);
    float* ce1;  cudaGetSymbolAddress((void**)&ce1, g_ce1);
    float* ce2;  cudaGetSymbolAddress((void**)&ce2, g_ce2);
    __nv_bfloat16 *wt1h, *wt1l, *wt2h, *wt2l;
    cudaGetSymbolAddress((void**)&wt1h, g_Wt1hi);
    cudaGetSymbolAddress((void**)&wt1l, g_Wt1lo);
    cudaGetSymbolAddress((void**)&wt2h, g_Wt2hi);
    cudaGetSymbolAddress((void**)&wt2l, g_Wt2lo);

    // setup: CSR + ce + W conversion
    zero_counts_kernel<<<(NN + 255) / 256, 256>>>();
    hist_kernel<<<(NE / 4 + 255) / 256, 256>>>(dst);
    scan_kernel<<<1, 1024>>>(We1, ae1, We2, ae2);
    scatter_kernel<<<(NE / 2 + 255) / 256, 256>>>(src, dst, edge_attr, edge_atten);
    convert_w_kernel<<<(128 * 256 + 256 * 256 + 255) / 256, 256>>>(W1, W2, wt1h, wt1l, wt2h, wt2l);

    run_layer(x, 128, wt1h, wt1l, asrc1, adst1, ce1, b1, hbuf, out_w1);
    run_layer(hbuf, 256, wt2h, wt2l, asrc2, adst2, ce2, b2, out_h, out_w2);
}

// round 8
// speedup vs baseline: 3.5589x; 1.1520x over previous
#include <cuda_runtime.h>
#include <cuda_bf16.h>
#include <cuda_fp16.h>
#include <math.h>
#include <stdint.h>

#define NN 20000
#define NE 640000
#define HD 4
#define CC 64
#define FO 256
#define NEG_SLOPE 0.2f

struct __align__(16) EdgeRec { int e; int s; float ea; float at; };

// ================= scratch =================
__device__ __align__(16) __half g_xh[(size_t)NN * FO];   // fp16: only the gather reads it
__device__ float g_h[(size_t)NN * FO];
__device__ float g_alpha_r[(size_t)NE * HD];   // logits, then exp values (in-place)
__device__ EdgeRec g_edge_r[NE];
__device__ float g_asrc[NN * HD];
__device__ float g_adst[NN * HD];
__device__ float g_ce1[HD];
__device__ float g_ce2[HD];
__device__ int   g_cnt[NN];
__device__ int   g_cursor[NN];
__device__ int   g_rowstart[NN + 1];
__device__ __align__(16) __nv_bfloat16 g_Wt1hi[256 * 128];
__device__ __align__(16) __nv_bfloat16 g_Wt1lo[256 * 128];
__device__ __align__(16) __nv_bfloat16 g_Wt2hi[256 * 256];
__device__ __align__(16) __nv_bfloat16 g_Wt2lo[256 * 256];

// ================= CSR build =================
__global__ void zero_counts_kernel() {
    int i = blockIdx.x * blockDim.x + threadIdx.x;
    if (i < NN) { g_cnt[i] = 0; g_cursor[i] = 0; }
}

__global__ void hist_kernel(const int* __restrict__ dst) {
    int e = (blockIdx.x * blockDim.x + threadIdx.x) * 4;
    if (e + 3 < NE) {
        int4 d = *(const int4*)(dst + e);
        atomicAdd(&g_cnt[d.x], 1);
        atomicAdd(&g_cnt[d.y], 1);
        atomicAdd(&g_cnt[d.z], 1);
        atomicAdd(&g_cnt[d.w], 1);
    }
}

// single-pass scan (1024 threads, 20 nodes/thread) + fused ce precompute
__global__ void scan_kernel(const float* __restrict__ We1, const float* __restrict__ ae1,
                            const float* __restrict__ We2, const float* __restrict__ ae2)
{
    int tid = threadIdx.x;
    int wq = tid >> 5, lane = tid & 31;
    if (wq < 8) {
        const float* We = (wq < 4) ? We1 : We2;
        const float* ae = (wq < 4) ? ae1 : ae2;
        float* ce = (wq < 4) ? g_ce1 : g_ce2;
        int h = wq & 3;
        float v = We[h * 64 + lane] * ae[h * 64 + lane]
                + We[h * 64 + lane + 32] * ae[h * 64 + lane + 32];
#pragma unroll
        for (int o = 16; o; o >>= 1) v += __shfl_xor_sync(0xffffffffu, v, o);
        if (lane == 0) ce[h] = v;
    }

    const int PER = 20;
    int base = tid * PER;
    int loc[PER];
    int sum = 0;
#pragma unroll
    for (int j = 0; j < PER; j++) {
        int i = base + j;
        int v = (i < NN) ? g_cnt[i] : 0;
        sum += v;
        loc[j] = sum;
    }
    int x = sum;
#pragma unroll
    for (int o = 1; o < 32; o <<= 1) {
        int t = __shfl_up_sync(0xffffffffu, x, o);
        if (lane >= o) x += t;
    }
    __shared__ int wsum[32];
    if (lane == 31) wsum[wq] = x;
    __syncthreads();
    if (wq == 0) {
        int y = (lane < 32) ? wsum[lane] : 0;
#pragma unroll
        for (int o = 1; o < 32; o <<= 1) {
            int t = __shfl_up_sync(0xffffffffu, y, o);
            if (lane >= o) y += t;
        }
        wsum[lane] = y;
    }
    __syncthreads();
    int excl = x - sum + (wq ? wsum[wq - 1] : 0);
    if (tid == 0) g_rowstart[0] = 0;
#pragma unroll
    for (int j = 0; j < PER; j++) {
        int i = base + j;
        if (i < NN) g_rowstart[i + 1] = excl + loc[j];
    }
}

// scatter: CSR-ordered EdgeRec stream, ILP-4
__global__ void scatter_kernel(const int* __restrict__ src,
                               const int* __restrict__ dst,
                               const float* __restrict__ edge_attr,
                               const float* __restrict__ edge_atten)
{
    int e = (blockIdx.x * blockDim.x + threadIdx.x) * 4;
    if (e + 3 < NE) {
        int4   d4 = *(const int4*)(dst + e);
        int4   s4 = *(const int4*)(src + e);
        float4 ea = *(const float4*)(edge_attr + e);
        float4 at = *(const float4*)(edge_atten + e);
        int p0 = g_rowstart[d4.x] + atomicAdd(&g_cursor[d4.x], 1);
        int p1 = g_rowstart[d4.y] + atomicAdd(&g_cursor[d4.y], 1);
        int p2 = g_rowstart[d4.z] + atomicAdd(&g_cursor[d4.z], 1);
        int p3 = g_rowstart[d4.w] + atomicAdd(&g_cursor[d4.w], 1);
        EdgeRec r0 = {e,     s4.x, ea.x, at.x};
        EdgeRec r1 = {e + 1, s4.y, ea.y, at.y};
        EdgeRec r2 = {e + 2, s4.z, ea.z, at.z};
        EdgeRec r3 = {e + 3, s4.w, ea.w, at.w};
        g_edge_r[p0] = r0;
        g_edge_r[p1] = r1;
        g_edge_r[p2] = r2;
        g_edge_r[p3] = r3;
    }
}

// ================= W transpose + bf16 split (both layers) =================
__global__ void convert_w_kernel(const float* __restrict__ W1,
                                 const float* __restrict__ W2,
                                 __nv_bfloat16* __restrict__ W1hi,
                                 __nv_bfloat16* __restrict__ W1lo,
                                 __nv_bfloat16* __restrict__ W2hi,
                                 __nv_bfloat16* __restrict__ W2lo)
{
    int idx = blockIdx.x * blockDim.x + threadIdx.x;
    if (idx < 128 * 256) {
        int k = idx >> 8, n = idx & 255;
        float v = W1[idx];
        __nv_bfloat16 h = __float2bfloat16_rn(v);
        W1hi[n * 128 + k] = h;
        W1lo[n * 128 + k] = __float2bfloat16_rn(v - __bfloat162float(h));
    } else if (idx < 128 * 256 + 256 * 256) {
        int i2 = idx - 128 * 256;
        int k = i2 >> 8, n = i2 & 255;
        float v = W2[i2];
        __nv_bfloat16 h = __float2bfloat16_rn(v);
        W2hi[n * 256 + k] = h;
        W2lo[n * 256 + k] = __float2bfloat16_rn(v - __bfloat162float(h));
    }
}

// ================= split-bf16 mma.sync GEMM + fused alpha dots =================
__device__ __forceinline__ void mma_bf16(float* c, uint32_t a0, uint32_t a1,
                                         uint32_t a2, uint32_t a3,
                                         uint32_t b0, uint32_t b1)
{
    asm volatile(
        "mma.sync.aligned.m16n8k16.row.col.f32.bf16.bf16.f32 "
        "{%0,%1,%2,%3}, {%4,%5,%6,%7}, {%8,%9}, {%0,%1,%2,%3};"
        : "+f"(c[0]), "+f"(c[1]), "+f"(c[2]), "+f"(c[3])
        : "r"(a0), "r"(a1), "r"(a2), "r"(a3), "r"(b0), "r"(b1));
}

#define KP 20  // uint32 pitch per 32-k row (80B rows, 16B-aligned)

__global__ __launch_bounds__(256) void gemm_mma_kernel(
    const float* __restrict__ A,
    const __nv_bfloat16* __restrict__ Bhi,
    const __nv_bfloat16* __restrict__ Blo,
    __half* __restrict__ C, int K,
    const float* __restrict__ asrc, const float* __restrict__ adst)
{
    __shared__ uint32_t As_hi[128][KP];
    __shared__ uint32_t As_lo[128][KP];
    __shared__ uint32_t Bs_hi[128][KP];
    __shared__ uint32_t Bs_lo[128][KP];

    int tid = threadIdx.x;
    int wid = tid >> 5, lane = tid & 31;
    int m0c = blockIdx.x * 128, n0c = blockIdx.y * 128;
    int wm0 = (wid >> 1) * 32, wn0 = (wid & 1) * 64;
    int lq = lane >> 2, lr = lane & 3;

    float acc[2][8][4];
#pragma unroll
    for (int mt = 0; mt < 2; mt++)
#pragma unroll
        for (int nt = 0; nt < 8; nt++)
#pragma unroll
            for (int j = 0; j < 4; j++) acc[mt][nt][j] = 0.f;

    int a_row = tid >> 1, a_half = tid & 1;
    int a_grow = m0c + a_row;
    bool a_ok = (a_grow < NN);
    int b_row = tid & 127, b_half = tid >> 7;

    const float* Abase = A + (size_t)a_grow * K + a_half * 16;
    const __nv_bfloat16* Bhbase = Bhi + (size_t)(n0c + b_row) * K + b_half * 16;
    const __nv_bfloat16* Blbase = Blo + (size_t)(n0c + b_row) * K + b_half * 16;

    float4 av[4];
    uint4 bvh0, bvh1, bvl0, bvl1;
#pragma unroll
    for (int j = 0; j < 4; j++)
        av[j] = a_ok ? *(const float4*)(Abase + j * 4)
                     : make_float4(0.f, 0.f, 0.f, 0.f);
    bvh0 = *(const uint4*)(Bhbase);
    bvh1 = *(const uint4*)(Bhbase + 8);
    bvl0 = *(const uint4*)(Blbase);
    bvl1 = *(const uint4*)(Blbase + 8);

    int nchunks = K >> 5;
    for (int c = 0; c < nchunks; c++) {
#pragma unroll
        for (int j = 0; j < 4; j++) {
            float4 v = av[j];
            __nv_bfloat162 h01 = __floats2bfloat162_rn(v.x, v.y);
            __nv_bfloat162 h23 = __floats2bfloat162_rn(v.z, v.w);
            __nv_bfloat162 l01 = __floats2bfloat162_rn(v.x - __low2float(h01),
                                                       v.y - __high2float(h01));
            __nv_bfloat162 l23 = __floats2bfloat162_rn(v.z - __low2float(h23),
                                                       v.w - __high2float(h23));
            int ci = (a_half * 16 + j * 4) >> 1;
            As_hi[a_row][ci]     = *(uint32_t*)&h01;
            As_hi[a_row][ci + 1] = *(uint32_t*)&h23;
            As_lo[a_row][ci]     = *(uint32_t*)&l01;
            As_lo[a_row][ci + 1] = *(uint32_t*)&l23;
        }
        {
            int ci = b_half * 8;
            *(uint4*)&Bs_hi[b_row][ci]     = bvh0;
            *(uint4*)&Bs_hi[b_row][ci + 4] = bvh1;
            *(uint4*)&Bs_lo[b_row][ci]     = bvl0;
            *(uint4*)&Bs_lo[b_row][ci + 4] = bvl1;
        }
        __syncthreads();

        if (c + 1 < nchunks) {
            int k0 = (c + 1) << 5;
#pragma unroll
            for (int j = 0; j < 4; j++)
                av[j] = a_ok ? *(const float4*)(Abase + k0 + j * 4)
                             : make_float4(0.f, 0.f, 0.f, 0.f);
            bvh0 = *(const uint4*)(Bhbase + k0);
            bvh1 = *(const uint4*)(Bhbase + k0 + 8);
            bvl0 = *(const uint4*)(Blbase + k0);
            bvl1 = *(const uint4*)(Blbase + k0 + 8);
        }

#pragma unroll
        for (int ks = 0; ks < 2; ks++) {
            int kb = ks * 8 + lr;
            uint32_t ah[2][4], al[2][4];
#pragma unroll
            for (int mt = 0; mt < 2; mt++) {
                int ra = wm0 + mt * 16 + lq, rb = ra + 8;
                ah[mt][0] = As_hi[ra][kb];     ah[mt][1] = As_hi[rb][kb];
                ah[mt][2] = As_hi[ra][kb + 4]; ah[mt][3] = As_hi[rb][kb + 4];
                al[mt][0] = As_lo[ra][kb];     al[mt][1] = As_lo[rb][kb];
                al[mt][2] = As_lo[ra][kb + 4]; al[mt][3] = As_lo[rb][kb + 4];
            }
#pragma unroll
            for (int nt = 0; nt < 8; nt++) {
                int nr = wn0 + nt * 8 + lq;
                uint32_t bh0 = Bs_hi[nr][kb], bh1 = Bs_hi[nr][kb + 4];
                uint32_t bl0 = Bs_lo[nr][kb], bl1 = Bs_lo[nr][kb + 4];
#pragma unroll
                for (int mt = 0; mt < 2; mt++) {
                    mma_bf16(acc[mt][nt], ah[mt][0], ah[mt][1], ah[mt][2], ah[mt][3], bh0, bh1);
                    mma_bf16(acc[mt][nt], ah[mt][0], ah[mt][1], ah[mt][2], ah[mt][3], bl0, bl1);
                    mma_bf16(acc[mt][nt], al[mt][0], al[mt][1], al[mt][2], al[mt][3], bh0, bh1);
                }
            }
        }
        __syncthreads();
    }

    // ---- C store (fp16) ----
#pragma unroll
    for (int mt = 0; mt < 2; mt++) {
        int row0 = m0c + wm0 + mt * 16 + lq;
#pragma unroll
        for (int nt = 0; nt < 8; nt++) {
            int col = n0c + wn0 + nt * 8 + 2 * lr;
            if (row0 < NN)
                *(__half2*)(C + (size_t)row0 * FO + col) =
                    __floats2half2_rn(acc[mt][nt][0], acc[mt][nt][1]);
            if (row0 + 8 < NN)
                *(__half2*)(C + (size_t)(row0 + 8) * FO + col) =
                    __floats2half2_rn(acc[mt][nt][2], acc[mt][nt][3]);
        }
    }

    // ---- fused alpha_src / alpha_dst (fp32 from regs) ----
    {
        int h = (n0c + wn0) >> 6;
        float ps0 = 0.f, ps1 = 0.f, ps2 = 0.f, ps3 = 0.f;
        float pd0 = 0.f, pd1 = 0.f, pd2 = 0.f, pd3 = 0.f;
#pragma unroll
        for (int nt = 0; nt < 8; nt++) {
            int c0 = nt * 8 + 2 * lr;
            float2 cs = *(const float2*)(asrc + h * 64 + c0);
            float2 cd = *(const float2*)(adst + h * 64 + c0);
            ps0 += acc[0][nt][0] * cs.x + acc[0][nt][1] * cs.y;
            ps1 += acc[0][nt][2] * cs.x + acc[0][nt][3] * cs.y;
            ps2 += acc[1][nt][0] * cs.x + acc[1][nt][1] * cs.y;
            ps3 += acc[1][nt][2] * cs.x + acc[1][nt][3] * cs.y;
            pd0 += acc[0][nt][0] * cd.x + acc[0][nt][1] * cd.y;
            pd1 += acc[0][nt][2] * cd.x + acc[0][nt][3] * cd.y;
            pd2 += acc[1][nt][0] * cd.x + acc[1][nt][1] * cd.y;
            pd3 += acc[1][nt][2] * cd.x + acc[1][nt][3] * cd.y;
        }
#pragma unroll
        for (int o = 1; o <= 2; o <<= 1) {
            ps0 += __shfl_xor_sync(0xffffffffu, ps0, o);
            ps1 += __shfl_xor_sync(0xffffffffu, ps1, o);
            ps2 += __shfl_xor_sync(0xffffffffu, ps2, o);
            ps3 += __shfl_xor_sync(0xffffffffu, ps3, o);
            pd0 += __shfl_xor_sync(0xffffffffu, pd0, o);
            pd1 += __shfl_xor_sync(0xffffffffu, pd1, o);
            pd2 += __shfl_xor_sync(0xffffffffu, pd2, o);
            pd3 += __shfl_xor_sync(0xffffffffu, pd3, o);
        }
        if (lr == 0) {
            int r = m0c + wm0 + lq;
            if (r < NN)      { g_asrc[r * 4 + h] = ps0;        g_adst[r * 4 + h] = pd0; }
            if (r + 8 < NN)  { g_asrc[(r + 8) * 4 + h] = ps1;  g_adst[(r + 8) * 4 + h] = pd1; }
            if (r + 16 < NN) { g_asrc[(r + 16) * 4 + h] = ps2; g_adst[(r + 16) * 4 + h] = pd2; }
            if (r + 24 < NN) { g_asrc[(r + 24) * 4 + h] = ps3; g_adst[(r + 24) * 4 + h] = pd3; }
        }
    }
}

// ================= fused: logits + softmax + fp16 gather, warp per dst ==========
__global__ __launch_bounds__(256) void fused_agg_kernel(
    const float* __restrict__ ce,
    const float* __restrict__ bias,
    float* __restrict__ out_h,
    float* __restrict__ out_w)
{
    __shared__ float s_w[8][32][4];
    __shared__ int   s_s[8][32];
    int wslot = threadIdx.x >> 5;
    int n = blockIdx.x * 8 + wslot;
    int lane = threadIdx.x & 31;
    if (n >= NN) return;
    int r0 = g_rowstart[n], r1 = g_rowstart[n + 1];

    float4 c   = *(const float4*)ce;
    float4 adn = *(const float4*)(g_adst + (size_t)n * 4);

    // ---- pass 1: logits + leaky relu + max ----
    float mx0 = -3.4e38f, mx1 = -3.4e38f, mx2 = -3.4e38f, mx3 = -3.4e38f;
    for (int i = r0 + lane; i < r1; i += 32) {
        EdgeRec er = g_edge_r[i];
        float4 as = *(const float4*)(g_asrc + (size_t)er.s * 4);
        float a0 = as.x + adn.x + er.ea * c.x;
        float a1 = as.y + adn.y + er.ea * c.y;
        float a2 = as.z + adn.z + er.ea * c.z;
        float a3 = as.w + adn.w + er.ea * c.w;
        a0 = a0 > 0.f ? a0 : NEG_SLOPE * a0;
        a1 = a1 > 0.f ? a1 : NEG_SLOPE * a1;
        a2 = a2 > 0.f ? a2 : NEG_SLOPE * a2;
        a3 = a3 > 0.f ? a3 : NEG_SLOPE * a3;
        *(float4*)(g_alpha_r + (size_t)i * 4) = make_float4(a0, a1, a2, a3);
        mx0 = fmaxf(mx0, a0); mx1 = fmaxf(mx1, a1);
        mx2 = fmaxf(mx2, a2); mx3 = fmaxf(mx3, a3);
    }
#pragma unroll
    for (int o = 16; o; o >>= 1) {
        mx0 = fmaxf(mx0, __shfl_xor_sync(0xffffffffu, mx0, o));
        mx1 = fmaxf(mx1, __shfl_xor_sync(0xffffffffu, mx1, o));
        mx2 = fmaxf(mx2, __shfl_xor_sync(0xffffffffu, mx2, o));
        mx3 = fmaxf(mx3, __shfl_xor_sync(0xffffffffu, mx3, o));
    }

    // ---- pass 2: exp in place + denom ----
    float dn0 = 0.f, dn1 = 0.f, dn2 = 0.f, dn3 = 0.f;
    for (int i = r0 + lane; i < r1; i += 32) {
        float4 a = *(const float4*)(g_alpha_r + (size_t)i * 4);
        float e0 = __expf(a.x - mx0), e1 = __expf(a.y - mx1);
        float e2 = __expf(a.z - mx2), e3 = __expf(a.w - mx3);
        *(float4*)(g_alpha_r + (size_t)i * 4) = make_float4(e0, e1, e2, e3);
        dn0 += e0; dn1 += e1; dn2 += e2; dn3 += e3;
    }
#pragma unroll
    for (int o = 16; o; o >>= 1) {
        dn0 += __shfl_xor_sync(0xffffffffu, dn0, o);
        dn1 += __shfl_xor_sync(0xffffffffu, dn1, o);
        dn2 += __shfl_xor_sync(0xffffffffu, dn2, o);
        dn3 += __shfl_xor_sync(0xffffffffu, dn3, o);
    }
    float inv0 = 1.f / (dn0 + 1e-16f);
    float inv1 = 1.f / (dn1 + 1e-16f);
    float inv2 = 1.f / (dn2 + 1e-16f);
    float inv3 = 1.f / (dn3 + 1e-16f);

    // ---- pass 3: weights + fp16 gather (lane owns 8 contiguous cols) ----
    int hsel = lane >> 3;   // head for this lane's 8 columns
    float acc0 = 0.f, acc1 = 0.f, acc2 = 0.f, acc3 = 0.f;
    float acc4 = 0.f, acc5 = 0.f, acc6 = 0.f, acc7 = 0.f;

    for (int base = r0; base < r1; base += 32) {
        int i = base + lane;
        int cnt = min(32, r1 - base);
        if (i < r1) {
            float4 ex = *(const float4*)(g_alpha_r + (size_t)i * 4);
            EdgeRec er = g_edge_r[i];
            float w0 = ex.x * inv0, w1 = ex.y * inv1;
            float w2 = ex.z * inv2, w3 = ex.w * inv3;
            *(float4*)(out_w + (size_t)er.e * 4) = make_float4(w0, w1, w2, w3);
            *(float4*)&s_w[wslot][lane][0] =
                make_float4(w0 * er.at, w1 * er.at, w2 * er.at, w3 * er.at);
            s_s[wslot][lane] = er.s;
        }
        __syncwarp();
        for (int j = 0; j < cnt; j++) {
            float w = s_w[wslot][j][hsel];
            int sc = s_s[wslot][j];
            uint4 v = *((const uint4*)(g_xh + (size_t)sc * FO) + lane);
            float2 f0 = __half22float2(*(__half2*)&v.x);
            float2 f1 = __half22float2(*(__half2*)&v.y);
            float2 f2 = __half22float2(*(__half2*)&v.z);
            float2 f3 = __half22float2(*(__half2*)&v.w);
            acc0 += w * f0.x; acc1 += w * f0.y;
            acc2 += w * f1.x; acc3 += w * f1.y;
            acc4 += w * f2.x; acc5 += w * f2.y;
            acc6 += w * f3.x; acc7 += w * f3.y;
        }
        __syncwarp();
    }

    float4 bA = *(const float4*)(bias + lane * 8);
    float4 bB = *(const float4*)(bias + lane * 8 + 4);
    float* orow = out_h + (size_t)n * FO + lane * 8;
    *(float4*)orow =
        make_float4(acc0 + bA.x, acc1 + bA.y, acc2 + bA.z, acc3 + bA.w);
    *(float4*)(orow + 4) =
        make_float4(acc4 + bB.x, acc5 + bB.y, acc6 + bB.z, acc7 + bB.w);
}

// ================= launch =================
static void run_layer(const float* xin, int Kdim,
                      const __nv_bfloat16* Whi, const __nv_bfloat16* Wlo,
                      const float* asrc, const float* adst,
                      const float* ce_dev, const float* b,
                      float* out_h, float* out_w)
{
    __half* xh;
    cudaGetSymbolAddress((void**)&xh, g_xh);
    dim3 ggrid((NN + 127) / 128, 2);
    gemm_mma_kernel<<<ggrid, 256>>>(xin, Whi, Wlo, xh, Kdim, asrc, adst);
    fused_agg_kernel<<<(NN + 7) / 8, 256>>>(ce_dev, b, out_h, out_w);
}

extern "C" void kernel_launch(void* const* d_in, const int* in_sizes, int n_in,
                              void* d_out, int out_size)
{
    const float* x          = (const float*)d_in[0];
    const int*   edge_index = (const int*)d_in[1];
    const float* edge_attr  = (const float*)d_in[3];
    const float* edge_atten = (const float*)d_in[4];
    const float* W1    = (const float*)d_in[5];
    const float* asrc1 = (const float*)d_in[6];
    const float* adst1 = (const float*)d_in[7];
    const float* We1   = (const float*)d_in[8];
    const float* ae1   = (const float*)d_in[9];
    const float* b1    = (const float*)d_in[10];
    const float* W2    = (const float*)d_in[11];
    const float* asrc2 = (const float*)d_in[12];
    const float* adst2 = (const float*)d_in[13];
    const float* We2   = (const float*)d_in[14];
    const float* ae2   = (const float*)d_in[15];
    const float* b2    = (const float*)d_in[16];

    const int* src = edge_index;
    const int* dst = edge_index + NE;

    float* out    = (float*)d_out;
    float* out_h  = out;
    float* out_w1 = out + (size_t)NN * FO;
    float* out_w2 = out_w1 + (size_t)NE * HD;

    float* hbuf; cudaGetSymbolAddress((void**)&hbuf, g_h);
    float* ce1;  cudaGetSymbolAddress((void**)&ce1, g_ce1);
    float* ce2;  cudaGetSymbolAddress((void**)&ce2, g_ce2);
    __nv_bfloat16 *wt1h, *wt1l, *wt2h, *wt2l;
    cudaGetSymbolAddress((void**)&wt1h, g_Wt1hi);
    cudaGetSymbolAddress((void**)&wt1l, g_Wt1lo);
    cudaGetSymbolAddress((void**)&wt2h, g_Wt2hi);
    cudaGetSymbolAddress((void**)&wt2l, g_Wt2lo);

    // setup: CSR + ce + W conversion
    zero_counts_kernel<<<(NN + 255) / 256, 256>>>();
    hist_kernel<<<(NE / 4 + 255) / 256, 256>>>(dst);
    scan_kernel<<<1, 1024>>>(We1, ae1, We2, ae2);
    scatter_kernel<<<(NE / 4 + 255) / 256, 256>>>(src, dst, edge_attr, edge_atten);
    convert_w_kernel<<<(128 * 256 + 256 * 256 + 255) / 256, 256>>>(W1, W2, wt1h, wt1l, wt2h, wt2l);

    run_layer(x, 128, wt1h, wt1l, asrc1, adst1, ce1, b1, hbuf, out_w1);
    run_layer(hbuf, 256, wt2h, wt2l, asrc2, adst2, ce2, b2, out_h, out_w2);
}